// round 13
// baseline (speedup 1.0000x reference)
#include <cuda_runtime.h>
#include <cstdint>
#include <math.h>

// Problem constants
#define BB 128
#define SS 256
#define HH 1024
#define EE 512
#define ENVD 896
#define VV 10000
#define INSZ 3456          // E + H + H + ENV
#define MATT (SS*BB)       // 32768
#define G4H 4096

// fp32 -> tf32 (rna) kept in a float container (low 13 mantissa bits zero).
__device__ __forceinline__ float tf32f(float x) {
    unsigned r;
    asm("cvt.rna.tf32.f32 %0, %1;" : "=r"(r) : "f"(x));
    return __uint_as_float(r);
}

__device__ __forceinline__ uint32_t smem_u32(const void* p) {
    uint32_t a;
    asm("{ .reg .u64 t; cvta.to.shared.u64 t, %1; cvt.u32.u64 %0, t; }" : "=r"(a) : "l"(p));
    return a;
}

// ---------------- scratch (device globals; DEVICE-CODE-ONLY references) ----------------
__device__ float g_x[BB*INSZ];          // LSTM input concat (tf32-rounded at write)
__device__ float g_hp[BB*HH];
__device__ float g_hc[BB*HH];
__device__ float g_spP[8*MATT];         // score partials, [n_tile][m]
__device__ float g_spC[8*MATT];
__device__ float g_wP[MATT];
__device__ float g_wC[MATT];
__device__ float g_gpart[5*BB*G4H];
__device__ float g_gates[BB*G4H];
__device__ float g_opart[2*BB*VV];
__device__ float g_h1[BB*HH];           // tf32-rounded (feeds out GEMM)
__device__ float g_c1[BB*HH];
// pre-rounded (tf32-in-fp32) GEMM operands
__device__ float g_encP[MATT*HH];
__device__ float g_encC[MATT*HH];
__device__ float g_Whp[HH*HH];
__device__ float g_Whc[HH*HH];
__device__ float g_Wep[HH*HH];
__device__ float g_Wec[HH*HH];
__device__ float g_Wih[INSZ*G4H];
__device__ float g_Whh[HH*G4H];
__device__ float g_Wo[HH*VV];
__device__ float g_h0r[BB*HH];

// ---------------- pre-round kernel: dst[i] = tf32_rna(src[i]), float4-wide ----------------
__global__ void __launch_bounds__(256) k_round(const float* __restrict__ src, int which, int n4)
{
    int i = blockIdx.x*256 + threadIdx.x;
    if (i >= n4) return;
    float* dst;
    switch (which) {
        case 0: dst = g_encP; break;
        case 1: dst = g_encC; break;
        case 2: dst = g_Whp;  break;
        case 3: dst = g_Whc;  break;
        case 4: dst = g_Wep;  break;
        case 5: dst = g_Wec;  break;
        case 6: dst = g_Wih;  break;
        case 7: dst = g_Whh;  break;
        case 8: dst = g_Wo;   break;
        default: dst = g_h0r; break;
    }
    float4 v = ((const float4*)src)[i];
    float4 w;
    w.x = tf32f(v.x); w.y = tf32f(v.y); w.z = tf32f(v.z); w.w = tf32f(v.w);
    ((float4*)dst)[i] = w;
}

// ---------------- tf32 mma.sync GEMM core, 3-stage cp.async pipeline ----------------
// Inputs are already tf32-rounded in gmem -> pure async copy, no CVT/STS in mainloop.
#define AS_LD 36
#define BS_LD 136
#define STAGE_F (128*AS_LD + 32*BS_LD)      // 8960 floats per stage
#define SMEM_BYTES (3*STAGE_F*4)            // 107520 bytes (3 stages)

__device__ __forceinline__ void mma_tf32(float* c, const unsigned* a, unsigned b0, unsigned b1) {
    asm volatile(
        "mma.sync.aligned.m16n8k8.row.col.f32.tf32.tf32.f32 "
        "{%0,%1,%2,%3},{%4,%5,%6,%7},{%8,%9},{%0,%1,%2,%3};"
        : "+f"(c[0]), "+f"(c[1]), "+f"(c[2]), "+f"(c[3])
        : "r"(a[0]), "r"(a[1]), "r"(a[2]), "r"(a[3]), "r"(b0), "r"(b1));
}

__device__ __forceinline__ void cpa16(uint32_t dst, const float* src) {
    asm volatile("cp.async.cg.shared.global [%0], [%1], 16;" :: "r"(dst), "l"(src));
}
__device__ __forceinline__ void cpa16z(uint32_t dst, const float* src, int bytes) {
    asm volatile("cp.async.cg.shared.global [%0], [%1], 16, %2;" :: "r"(dst), "l"(src), "r"(bytes));
}
#define CPA_COMMIT() asm volatile("cp.async.commit_group;" ::: "memory")
#define CPA_WAIT1()  asm volatile("cp.async.wait_group 1;" ::: "memory")

__device__ __forceinline__ void issue_tile_async(
    uint32_t stage_u,
    const float* __restrict__ A, int lda,
    const float* __restrict__ Wn, int ldw,
    int kt, int nvalid, int t)
{
    uint32_t As_u = stage_u;
    uint32_t Bs_u = stage_u + 128*AS_LD*4;
    #pragma unroll
    for (int j = 0; j < 4; j++) {
        int idx = t + 256*j;
        int row = idx >> 3, cq = (idx & 7) << 2;
        cpa16(As_u + (uint32_t)(row*AS_LD + cq)*4, A + (size_t)row*lda + kt + cq);
    }
    #pragma unroll
    for (int j = 0; j < 4; j++) {
        int idx = t + 256*j;
        int kr = idx >> 5, nq = (idx & 31) << 2;
        const float* src = Wn + (size_t)(kt + kr)*ldw + nq;
        uint32_t dst = Bs_u + (uint32_t)(kr*BS_LD + nq)*4;
        if (nvalid >= 128) {
            cpa16(dst, src);
        } else {
            int rem = nvalid - nq;
            int bytes = rem >= 4 ? 16 : (rem > 0 ? rem*4 : 0);
            cpa16z(dst, rem > 0 ? src : Wn, bytes);
        }
    }
}

__device__ __forceinline__ void compute_tile(
    const float* __restrict__ As, const float* __restrict__ Bs,
    float (&acc)[2][8][4], int mwarp, int nwarp, int lq, int lp)
{
    #pragma unroll
    for (int k8 = 0; k8 < 32; k8 += 8) {
        unsigned a[2][4];
        #pragma unroll
        for (int mt = 0; mt < 2; mt++) {
            int r = mwarp*32 + mt*16 + lq;
            int c = k8 + lp;
            a[mt][0] = __float_as_uint(As[r*AS_LD + c]);
            a[mt][1] = __float_as_uint(As[(r+8)*AS_LD + c]);
            a[mt][2] = __float_as_uint(As[r*AS_LD + c + 4]);
            a[mt][3] = __float_as_uint(As[(r+8)*AS_LD + c + 4]);
        }
        #pragma unroll
        for (int nt = 0; nt < 8; nt++) {
            int n  = nwarp*64 + nt*8 + lq;
            int kb = k8 + lp;
            unsigned b0 = __float_as_uint(Bs[kb*BS_LD + n]);
            unsigned b1 = __float_as_uint(Bs[(kb+4)*BS_LD + n]);
            mma_tf32(acc[0][nt], a[0], b0, b1);
            mma_tf32(acc[1][nt], a[1], b0, b1);
        }
    }
}

__device__ __forceinline__ void mma_core_async(
    const float* __restrict__ A, int lda,
    const float* __restrict__ Wn, int ldw,
    int k0, int k1, int nvalid,
    float (&acc)[2][8][4], float* smp)
{
    const int t = threadIdx.x;
    const int lane = t & 31, wid = t >> 5;
    const int mwarp = wid & 3, nwarp = wid >> 2;
    const int lq = lane >> 2, lp = lane & 3;
    const uint32_t smp_u = smem_u32(smp);
    const int nsteps = (k1 - k0) >> 5;

    // prologue: stages 0 and 1
    issue_tile_async(smp_u, A, lda, Wn, ldw, k0, nvalid, t);
    CPA_COMMIT();
    if (nsteps > 1)
        issue_tile_async(smp_u + STAGE_F*4, A, lda, Wn, ldw, k0 + 32, nvalid, t);
    CPA_COMMIT();

    for (int i = 0; i < nsteps; i++) {
        CPA_WAIT1();              // own groups <=1 pending -> stage i complete
        __syncthreads();          // all warps' stage-i copies visible; buf (i+2)%3 free
        if (i + 2 < nsteps) {
            int s = (i + 2) % 3;
            issue_tile_async(smp_u + (uint32_t)s*STAGE_F*4, A, lda, Wn, ldw,
                             k0 + 32*(i+2), nvalid, t);
        }
        CPA_COMMIT();             // unconditional: keeps group ids == stage ids
        int cs = i % 3;
        compute_tile(smp + cs*STAGE_F, smp + cs*STAGE_F + 128*AS_LD,
                     acc, mwarp, nwarp, lq, lp);
    }
}

// ---------------- embedding gather + environment copy (tf32-rounded into x) ----------------
__global__ void __launch_bounds__(256) k_embed(
    const int* __restrict__ ids, const float* __restrict__ emb,
    const float* __restrict__ env)
{
    int b = blockIdx.x, t = threadIdx.x;
    int id = ids[b];
    float* xr = g_x + (size_t)b*INSZ;
    for (int c = t; c < EE; c += 256)   xr[c]        = tf32f(emb[(size_t)id*EE + c]);
    for (int c = t; c < ENVD; c += 256) xr[2560 + c] = tf32f(env[(size_t)b*ENVD + c]);
}

// ---------------- h projections: g_hp/g_hc = h@W + b1 + b2 ----------------
__global__ void __launch_bounds__(256) k_hproj(
    const float* __restrict__ b1p, const float* __restrict__ b2p,
    const float* __restrict__ b1c, const float* __restrict__ b2c)
{
    extern __shared__ float smem[];
    float acc[2][8][4] = {};
    int n0 = blockIdx.x * 128;
    const float* W  = blockIdx.y ? g_Whc : g_Whp;
    const float* b1 = blockIdx.y ? b1c : b1p;
    const float* b2 = blockIdx.y ? b2c : b2p;
    float* out      = blockIdx.y ? g_hc : g_hp;

    mma_core_async(g_h0r, HH, W + n0, HH, 0, HH, 128, acc, smem);

    int t = threadIdx.x, lane = t & 31, wid = t >> 5;
    int mwarp = wid & 3, nwarp = wid >> 2, lq = lane >> 2, lp = lane & 3;
    #pragma unroll
    for (int mt = 0; mt < 2; mt++)
        #pragma unroll
        for (int nt = 0; nt < 8; nt++) {
            int r  = mwarp*32 + mt*16 + lq;
            int cb = n0 + nwarp*64 + nt*8 + lp*2;
            out[(size_t)r*HH + cb]       = acc[mt][nt][0] + b1[cb]   + b2[cb];
            out[(size_t)r*HH + cb+1]     = acc[mt][nt][1] + b1[cb+1] + b2[cb+1];
            out[(size_t)(r+8)*HH + cb]   = acc[mt][nt][2] + b1[cb]   + b2[cb];
            out[(size_t)(r+8)*HH + cb+1] = acc[mt][nt][3] + b1[cb+1] + b2[cb+1];
        }
}

// ---------------- fused attention: U-tile GEMM + tanh·wa partial-score epilogue ----------------
__global__ void __launch_bounds__(256) k_attn_score(
    const float* __restrict__ wa, int sel)
{
    extern __shared__ float smem[];
    __shared__ float red[128][8];
    float acc[2][8][4] = {};
    int n0 = blockIdx.x * 128;
    int m0 = blockIdx.y * 128;

    const float* enc = sel ? g_encC : g_encP;
    const float* W   = sel ? g_Wec  : g_Wep;

    mma_core_async(enc + (size_t)m0*HH, HH, W + n0, HH, 0, HH, 128, acc, smem);

    const float* hp    = sel ? g_hc : g_hp;
    float*       spart = sel ? g_spC : g_spP;

    int t = threadIdx.x, lane = t & 31, wid = t >> 5;
    int mwarp = wid & 3, nwarp = wid >> 2, lq = lane >> 2, lp = lane & 3;

    float part[2][2] = {};
    #pragma unroll
    for (int mt = 0; mt < 2; mt++) {
        int r0 = mwarp*32 + mt*16 + lq;
        const float* hp0 = hp + (size_t)r0*HH;
        const float* hp8 = hp + (size_t)(r0+8)*HH;
        #pragma unroll
        for (int nt = 0; nt < 8; nt++) {
            int cb = n0 + nwarp*64 + nt*8 + lp*2;
            float w0 = wa[cb], w1 = wa[cb+1];
            part[mt][0] += tanhf(acc[mt][nt][0] + hp0[cb])   * w0
                         + tanhf(acc[mt][nt][1] + hp0[cb+1]) * w1;
            part[mt][1] += tanhf(acc[mt][nt][2] + hp8[cb])   * w0
                         + tanhf(acc[mt][nt][3] + hp8[cb+1]) * w1;
        }
    }
    int slot = nwarp*4 + lp;
    #pragma unroll
    for (int mt = 0; mt < 2; mt++) {
        red[mwarp*32 + mt*16 + lq][slot]     = part[mt][0];
        red[mwarp*32 + mt*16 + lq + 8][slot] = part[mt][1];
    }
    __syncthreads();
    if (t < 128) {
        float s = 0.f;
        #pragma unroll
        for (int p = 0; p < 8; p++) s += red[t][p];
        spart[(size_t)blockIdx.x*MATT + m0 + t] = s;
    }
}

// ---------------- softmax over S per batch row (sums 8 n-tile partials) ----------------
__global__ void __launch_bounds__(256) k_softmax(
    const float* __restrict__ b_a, int sel)
{
    const float* spart = sel ? g_spC : g_spP;
    float*       wout  = sel ? g_wC : g_wP;
    int b = blockIdx.x, s = threadIdx.x;   // 256 threads == S
    float sc = *b_a;
    #pragma unroll
    for (int p = 0; p < 8; p++) sc += spart[(size_t)p*MATT + s*BB + b];

    __shared__ float sm[256];
    sm[s] = sc; __syncthreads();
    for (int o = 128; o > 0; o >>= 1) {
        if (s < o) sm[s] = fmaxf(sm[s], sm[s+o]);
        __syncthreads();
    }
    float mx = sm[0]; __syncthreads();
    float e = expf(sc - mx);
    sm[s] = e; __syncthreads();
    for (int o = 128; o > 0; o >>= 1) {
        if (s < o) sm[s] += sm[s+o];
        __syncthreads();
    }
    wout[s*BB + b] = e / sm[0];
}

// ---------------- context: ctx[b,:] = sum_s w[s,b]*enc[s,b,:] -> g_x (tf32-rounded) ----------------
__global__ void __launch_bounds__(256) k_context(
    const float* __restrict__ enc, int sel)
{
    const float* w  = sel ? g_wC : g_wP;
    const int   off = sel ? 1536 : 512;
    int b = blockIdx.x, t = threadIdx.x;
    __shared__ float ws[256];
    ws[t] = w[t*BB + b];
    __syncthreads();
    const float4* e4 = (const float4*)enc;
    float4 acc = make_float4(0.f, 0.f, 0.f, 0.f);
    #pragma unroll 8
    for (int s = 0; s < SS; s++) {
        float wv = ws[s];
        float4 v = e4[((size_t)(s*BB + b))*(HH/4) + t];
        acc.x = fmaf(wv, v.x, acc.x);
        acc.y = fmaf(wv, v.y, acc.y);
        acc.z = fmaf(wv, v.z, acc.z);
        acc.w = fmaf(wv, v.w, acc.w);
    }
    float4 rr;
    rr.x = tf32f(acc.x); rr.y = tf32f(acc.y); rr.z = tf32f(acc.z); rr.w = tf32f(acc.w);
    *(float4*)(g_x + (size_t)b*INSZ + off + t*4) = rr;
}

// ---------------- gates GEMM, K split into 5 chunks ----------------
__global__ void __launch_bounds__(256) k_gates_part()
{
    extern __shared__ float smem[];
    float acc[2][8][4] = {};
    int n0 = blockIdx.x * 128;
    int ch = blockIdx.y;     // 0..3: W_ih chunks of 864 (27 k-steps), 4: W_hh
    if (ch < 4)
        mma_core_async(g_x, INSZ, g_Wih + n0, G4H, ch*864, (ch+1)*864, 128, acc, smem);
    else
        mma_core_async(g_h0r, HH, g_Whh + n0, G4H, 0, HH, 128, acc, smem);

    int t = threadIdx.x, lane = t & 31, wid = t >> 5;
    int mwarp = wid & 3, nwarp = wid >> 2, lq = lane >> 2, lp = lane & 3;
    float* dst = g_gpart + (size_t)ch*BB*G4H;
    #pragma unroll
    for (int mt = 0; mt < 2; mt++)
        #pragma unroll
        for (int nt = 0; nt < 8; nt++) {
            int r  = mwarp*32 + mt*16 + lq;
            int cb = n0 + nwarp*64 + nt*8 + lp*2;
            *(float2*)(dst + (size_t)r*G4H + cb)     = make_float2(acc[mt][nt][0], acc[mt][nt][1]);
            *(float2*)(dst + (size_t)(r+8)*G4H + cb) = make_float2(acc[mt][nt][2], acc[mt][nt][3]);
        }
}

__global__ void __launch_bounds__(256) k_gates_reduce(
    const float* __restrict__ b_ih, const float* __restrict__ b_hh)
{
    int idx = blockIdx.x*256 + threadIdx.x;
    int n = idx & (G4H-1);
    float s = b_ih[n] + b_hh[n];
    #pragma unroll
    for (int p = 0; p < 5; p++) s += g_gpart[(size_t)p*BB*G4H + idx];
    g_gates[idx] = s;
}

// ---------------- LSTM cell elementwise (double transcendentals: exact) ----------------
__global__ void __launch_bounds__(256) k_lstm(
    const float* __restrict__ c0, float* __restrict__ d_out, int write_out)
{
    int idx = blockIdx.x*256 + threadIdx.x;
    int b = idx >> 10, n = idx & 1023;
    const float* g = g_gates + (size_t)b*G4H;
    double gi = g[n], gf = g[1024+n], gg = g[2048+n], go = g[3072+n];
    double si = 1.0/(1.0 + exp(-gi));
    double sf = 1.0/(1.0 + exp(-gf));
    double so = 1.0/(1.0 + exp(-go));
    double c1 = sf * (double)c0[idx] + si * tanh(gg);
    double h1 = so * tanh(c1);
    float h1f = (float)h1;
    g_h1[idx] = tf32f(h1f);           // rounded copy feeds the out GEMM
    g_c1[idx] = (float)c1;
    if (write_out) {
        d_out[1280000 + idx] = h1f;   // exact
        d_out[1411072 + idx] = (float)c1;
    }
}

// ---------------- output GEMM, K split 2, N bounds ----------------
__global__ void __launch_bounds__(256) k_out_part()
{
    extern __shared__ float smem[];
    float acc[2][8][4] = {};
    int n0 = blockIdx.x * 128;
    int nvalid = VV - n0; if (nvalid > 128) nvalid = 128;
    int ks = blockIdx.y;
    mma_core_async(g_h1, HH, g_Wo + n0, VV, ks*512, (ks+1)*512, nvalid, acc, smem);

    int t = threadIdx.x, lane = t & 31, wid = t >> 5;
    int mwarp = wid & 3, nwarp = wid >> 2, lq = lane >> 2, lp = lane & 3;
    float* dst = g_opart + (size_t)ks*BB*VV;
    #pragma unroll
    for (int mt = 0; mt < 2; mt++)
        #pragma unroll
        for (int nt = 0; nt < 8; nt++) {
            int r  = mwarp*32 + mt*16 + lq;
            int cb = n0 + nwarp*64 + nt*8 + lp*2;
            if (cb + 1 < VV) {
                *(float2*)(dst + (size_t)r*VV + cb)     = make_float2(acc[mt][nt][0], acc[mt][nt][1]);
                *(float2*)(dst + (size_t)(r+8)*VV + cb) = make_float2(acc[mt][nt][2], acc[mt][nt][3]);
            }
        }
}

__global__ void __launch_bounds__(256) k_out_reduce(
    const float* __restrict__ b_out, float* __restrict__ out)
{
    int idx = blockIdx.x*256 + threadIdx.x;
    if (idx < BB*VV) {
        int n = idx % VV;
        out[idx] = g_opart[idx] + g_opart[(size_t)BB*VV + idx] + b_out[n];
    }
}

// ---------------- launch ----------------
extern "C" void kernel_launch(void* const* d_in, const int* in_sizes, int n_in,
                              void* d_out, int out_size)
{
    const int*   ids  = (const int*)d_in[0];
    const float* prev = (const float*)d_in[1];
    const float* encc = (const float*)d_in[2];
    const float* env  = (const float*)d_in[3];
    const float* h0   = (const float*)d_in[4];
    const float* c0   = (const float*)d_in[5];
    const float* emb  = (const float*)d_in[6];
    const float* W_hp = (const float*)d_in[7];
    const float* b_hp = (const float*)d_in[8];
    const float* W_ep = (const float*)d_in[9];
    const float* b_ep = (const float*)d_in[10];
    const float* w_ap = (const float*)d_in[11];
    const float* b_ap = (const float*)d_in[12];
    const float* W_hc = (const float*)d_in[13];
    const float* b_hc = (const float*)d_in[14];
    const float* W_ec = (const float*)d_in[15];
    const float* b_ec = (const float*)d_in[16];
    const float* w_ac = (const float*)d_in[17];
    const float* b_ac = (const float*)d_in[18];

    const float* W_ih = (const float*)d_in[19];
    const float* W_hh; const float* b_ih; const float* b_hh;
    if (in_sizes[20] == 1024*4096) {
        W_hh = (const float*)d_in[20];
        b_ih = (const float*)d_in[21];
        b_hh = (const float*)d_in[22];
    } else {
        b_ih = (const float*)d_in[20];
        W_hh = (const float*)d_in[21];
        b_hh = (const float*)d_in[22];
    }
    const float* W_out = (const float*)d_in[23];
    const float* b_out = (const float*)d_in[24];

    float* out = (float*)d_out;
    int write_state = (out_size >= 1542144) ? 1 : 0;

    // Raise dynamic-smem limits (host-side attribute; idempotent, capture-safe).
    cudaFuncSetAttribute(k_hproj,      cudaFuncAttributeMaxDynamicSharedMemorySize, SMEM_BYTES);
    cudaFuncSetAttribute(k_attn_score, cudaFuncAttributeMaxDynamicSharedMemorySize, SMEM_BYTES);
    cudaFuncSetAttribute(k_gates_part, cudaFuncAttributeMaxDynamicSharedMemorySize, SMEM_BYTES);
    cudaFuncSetAttribute(k_out_part,   cudaFuncAttributeMaxDynamicSharedMemorySize, SMEM_BYTES);

    // 0. pre-round all GEMM operands to tf32 (RNA) once
    k_round<<<(8388608+255)/256, 256>>>(prev,  0, 8388608);   // enc prev
    k_round<<<(8388608+255)/256, 256>>>(encc,  1, 8388608);   // enc cur
    k_round<<<(262144+255)/256, 256>>>(W_hp,  2, 262144);
    k_round<<<(262144+255)/256, 256>>>(W_hc,  3, 262144);
    k_round<<<(262144+255)/256, 256>>>(W_ep,  4, 262144);
    k_round<<<(262144+255)/256, 256>>>(W_ec,  5, 262144);
    k_round<<<(3538944+255)/256, 256>>>(W_ih, 6, 3538944);
    k_round<<<(1048576+255)/256, 256>>>(W_hh, 7, 1048576);
    k_round<<<(2560000+255)/256, 256>>>(W_out,8, 2560000);
    k_round<<<(32768+255)/256, 256>>>(h0,     9, 32768);

    k_embed<<<BB, 256>>>(ids, emb, env);
    k_hproj<<<dim3(8,2), 256, SMEM_BYTES>>>(b_hp, b_ep, b_hc, b_ec);
    k_attn_score<<<dim3(8,256), 256, SMEM_BYTES>>>(w_ap, 0);
    k_attn_score<<<dim3(8,256), 256, SMEM_BYTES>>>(w_ac, 1);
    k_softmax<<<BB, 256>>>(b_ap, 0);
    k_softmax<<<BB, 256>>>(b_ac, 1);
    k_context<<<BB, 256>>>(prev, 0);
    k_context<<<BB, 256>>>(encc, 1);
    k_gates_part<<<dim3(32,5), 256, SMEM_BYTES>>>();
    k_gates_reduce<<<(BB*G4H)/256, 256>>>(b_ih, b_hh);
    k_lstm<<<(BB*HH)/256, 256>>>(c0, out, write_state);
    k_out_part<<<dim3(79,2), 256, SMEM_BYTES>>>();
    k_out_reduce<<<(BB*VV + 255)/256, 256>>>(b_out, out);
}

// round 14
// speedup vs baseline: 1.3894x; 1.3894x over previous
#include <cuda_runtime.h>
#include <cuda_bf16.h>
#include <cstdint>
#include <math.h>

// Problem constants
#define BB 128
#define SS 256
#define HH 1024
#define EE 512
#define ENVD 896
#define VV 10000
#define INSZ 3456          // E + H + H + ENV
#define MATT (SS*BB)       // 32768
#define G4H 4096

// fp32 -> tf32 (rna) kept in a float container.
__device__ __forceinline__ float tf32f(float x) {
    unsigned r;
    asm("cvt.rna.tf32.f32 %0, %1;" : "=r"(r) : "f"(x));
    return __uint_as_float(r);
}
__device__ __forceinline__ unsigned short bfbits(float x) {
    __nv_bfloat16 h = __float2bfloat16_rn(x);
    return *reinterpret_cast<unsigned short*>(&h);
}
__device__ __forceinline__ uint32_t smem_u32(const void* p) {
    uint32_t a;
    asm("{ .reg .u64 t; cvta.to.shared.u64 t, %1; cvt.u32.u64 %0, t; }" : "=r"(a) : "l"(p));
    return a;
}

// ---------------- scratch (device globals; DEVICE-CODE-ONLY references) ----------------
__device__ float g_x[BB*INSZ];
__device__ float g_hp[BB*HH];
__device__ float g_hc[BB*HH];
__device__ float g_spP[8*MATT];
__device__ float g_spC[8*MATT];
__device__ float g_wP[MATT];
__device__ float g_wC[MATT];
__device__ float g_gpart[5*BB*G4H];
__device__ float g_gates[BB*G4H];
__device__ float g_opart[2*BB*VV];
__device__ float g_h1[BB*HH];
__device__ float g_c1[BB*HH];
// tf32-pre-rounded operands (gates / out / hproj)
__device__ float g_Whp[HH*HH];
__device__ float g_Whc[HH*HH];
__device__ float g_Wih[INSZ*G4H];
__device__ float g_Whh[HH*G4H];
__device__ float g_Wo[HH*VV];
__device__ float g_h0r[BB*HH];
// bf16 operands for attention GEMM
__device__ __nv_bfloat16 g_encPb[(size_t)MATT*HH];
__device__ __nv_bfloat16 g_encCb[(size_t)MATT*HH];
__device__ __nv_bfloat16 g_WepT[HH*HH];   // transposed [n][k]
__device__ __nv_bfloat16 g_WecT[HH*HH];

// ---------------- prep kernels ----------------
__global__ void __launch_bounds__(256) k_round(const float* __restrict__ src, int which, int n4)
{
    int i = blockIdx.x*256 + threadIdx.x;
    if (i >= n4) return;
    float* dst;
    switch (which) {
        case 0: dst = g_Whp; break;
        case 1: dst = g_Whc; break;
        case 2: dst = g_Wih; break;
        case 3: dst = g_Whh; break;
        case 4: dst = g_Wo;  break;
        default: dst = g_h0r; break;
    }
    float4 v = ((const float4*)src)[i];
    float4 w;
    w.x = tf32f(v.x); w.y = tf32f(v.y); w.z = tf32f(v.z); w.w = tf32f(v.w);
    ((float4*)dst)[i] = w;
}

__global__ void __launch_bounds__(256) k_enc_bf16(const float* __restrict__ src, int sel)
{
    size_t i = (size_t)blockIdx.x*256 + threadIdx.x;   // float4 index, MATT*HH/4 total
    float4 v = ((const float4*)src)[i];
    __nv_bfloat16* dst = sel ? g_encCb : g_encPb;
    uint2 o;
    o.x = (uint32_t)bfbits(v.x) | ((uint32_t)bfbits(v.y) << 16);
    o.y = (uint32_t)bfbits(v.z) | ((uint32_t)bfbits(v.w) << 16);
    ((uint2*)dst)[i] = o;
}

// transpose W [k][n] fp32 -> Wt [n][k] bf16 (32x32 tiles via smem)
__global__ void __launch_bounds__(256) k_wT(const float* __restrict__ W, int sel)
{
    __shared__ float tile[32][33];
    int n0 = blockIdx.x*32, k0 = blockIdx.y*32;
    int tx = threadIdx.x & 31, ty = threadIdx.x >> 5;   // 32 x 8
    #pragma unroll
    for (int i = 0; i < 32; i += 8)
        tile[ty+i][tx] = W[(size_t)(k0+ty+i)*HH + n0+tx];
    __syncthreads();
    __nv_bfloat16* Wt = sel ? g_WecT : g_WepT;
    #pragma unroll
    for (int i = 0; i < 32; i += 8)
        Wt[(size_t)(n0+ty+i)*HH + k0+tx] = __float2bfloat16_rn(tile[tx][ty+i]);
}

// ---------------- cp.async primitives ----------------
__device__ __forceinline__ void cpa16(uint32_t dst, const void* src) {
    asm volatile("cp.async.cg.shared.global [%0], [%1], 16;" :: "r"(dst), "l"(src));
}
__device__ __forceinline__ void cpa16z(uint32_t dst, const void* src, int bytes) {
    asm volatile("cp.async.cg.shared.global [%0], [%1], 16, %2;" :: "r"(dst), "l"(src), "r"(bytes));
}
#define CPA_COMMIT() asm volatile("cp.async.commit_group;" ::: "memory")
#define CPA_WAIT1()  asm volatile("cp.async.wait_group 1;" ::: "memory")

// ---------------- tf32 mma.sync GEMM core, 3-stage cp.async (hproj/gates/out) ----------------
#define AS_LD 36
#define BS_LD 136
#define STAGE_F (128*AS_LD + 32*BS_LD)      // 8960 floats per stage
#define SMEM_BYTES (3*STAGE_F*4)            // 107520 bytes

__device__ __forceinline__ void mma_tf32(float* c, const unsigned* a, unsigned b0, unsigned b1) {
    asm volatile(
        "mma.sync.aligned.m16n8k8.row.col.f32.tf32.tf32.f32 "
        "{%0,%1,%2,%3},{%4,%5,%6,%7},{%8,%9},{%0,%1,%2,%3};"
        : "+f"(c[0]), "+f"(c[1]), "+f"(c[2]), "+f"(c[3])
        : "r"(a[0]), "r"(a[1]), "r"(a[2]), "r"(a[3]), "r"(b0), "r"(b1));
}

__device__ __forceinline__ void issue_tile_async(
    uint32_t stage_u,
    const float* __restrict__ A, int lda,
    const float* __restrict__ Wn, int ldw,
    int kt, int nvalid, int t)
{
    uint32_t As_u = stage_u;
    uint32_t Bs_u = stage_u + 128*AS_LD*4;
    #pragma unroll
    for (int j = 0; j < 4; j++) {
        int idx = t + 256*j;
        int row = idx >> 3, cq = (idx & 7) << 2;
        cpa16(As_u + (uint32_t)(row*AS_LD + cq)*4, A + (size_t)row*lda + kt + cq);
    }
    #pragma unroll
    for (int j = 0; j < 4; j++) {
        int idx = t + 256*j;
        int kr = idx >> 5, nq = (idx & 31) << 2;
        const float* src = Wn + (size_t)(kt + kr)*ldw + nq;
        uint32_t dst = Bs_u + (uint32_t)(kr*BS_LD + nq)*4;
        if (nvalid >= 128) {
            cpa16(dst, src);
        } else {
            int rem = nvalid - nq;
            int bytes = rem >= 4 ? 16 : (rem > 0 ? rem*4 : 0);
            cpa16z(dst, rem > 0 ? src : Wn, bytes);
        }
    }
}

__device__ __forceinline__ void compute_tile(
    const float* __restrict__ As, const float* __restrict__ Bs,
    float (&acc)[2][8][4], int mwarp, int nwarp, int lq, int lp)
{
    #pragma unroll
    for (int k8 = 0; k8 < 32; k8 += 8) {
        unsigned a[2][4];
        #pragma unroll
        for (int mt = 0; mt < 2; mt++) {
            int r = mwarp*32 + mt*16 + lq;
            int c = k8 + lp;
            a[mt][0] = __float_as_uint(As[r*AS_LD + c]);
            a[mt][1] = __float_as_uint(As[(r+8)*AS_LD + c]);
            a[mt][2] = __float_as_uint(As[r*AS_LD + c + 4]);
            a[mt][3] = __float_as_uint(As[(r+8)*AS_LD + c + 4]);
        }
        #pragma unroll
        for (int nt = 0; nt < 8; nt++) {
            int n  = nwarp*64 + nt*8 + lq;
            int kb = k8 + lp;
            unsigned b0 = __float_as_uint(Bs[kb*BS_LD + n]);
            unsigned b1 = __float_as_uint(Bs[(kb+4)*BS_LD + n]);
            mma_tf32(acc[0][nt], a[0], b0, b1);
            mma_tf32(acc[1][nt], a[1], b0, b1);
        }
    }
}

__device__ __forceinline__ void mma_core_async(
    const float* __restrict__ A, int lda,
    const float* __restrict__ Wn, int ldw,
    int k0, int k1, int nvalid,
    float (&acc)[2][8][4], float* smp)
{
    const int t = threadIdx.x;
    const int lane = t & 31, wid = t >> 5;
    const int mwarp = wid & 3, nwarp = wid >> 2;
    const int lq = lane >> 2, lp = lane & 3;
    const uint32_t smp_u = smem_u32(smp);
    const int nsteps = (k1 - k0) >> 5;

    issue_tile_async(smp_u, A, lda, Wn, ldw, k0, nvalid, t);
    CPA_COMMIT();
    if (nsteps > 1)
        issue_tile_async(smp_u + STAGE_F*4, A, lda, Wn, ldw, k0 + 32, nvalid, t);
    CPA_COMMIT();

    for (int i = 0; i < nsteps; i++) {
        CPA_WAIT1();
        __syncthreads();
        if (i + 2 < nsteps) {
            int s = (i + 2) % 3;
            issue_tile_async(smp_u + (uint32_t)s*STAGE_F*4, A, lda, Wn, ldw,
                             k0 + 32*(i+2), nvalid, t);
        }
        CPA_COMMIT();
        int cs = i % 3;
        compute_tile(smp + cs*STAGE_F, smp + cs*STAGE_F + 128*AS_LD,
                     acc, mwarp, nwarp, lq, lp);
    }
}

// ---------------- bf16 mma.sync GEMM core, 3-stage cp.async (attention) ----------------
// A: [m][k] bf16, Bt: [n][k] bf16 (pre-transposed). Tile 128x128, K-step 32.
#define ABS_LD 40                            // bf16 elems/row (80B, conflict-free)
#define BSTAGE (2*128*ABS_LD*2)              // A+B stage bytes = 20480
#define ATTN_SMEM (3*BSTAGE)                 // 61440

__device__ __forceinline__ void mma_bf16(float* c, const unsigned* a, unsigned b0, unsigned b1) {
    asm volatile(
        "mma.sync.aligned.m16n8k16.row.col.f32.bf16.bf16.f32 "
        "{%0,%1,%2,%3},{%4,%5,%6,%7},{%8,%9},{%0,%1,%2,%3};"
        : "+f"(c[0]), "+f"(c[1]), "+f"(c[2]), "+f"(c[3])
        : "r"(a[0]), "r"(a[1]), "r"(a[2]), "r"(a[3]), "r"(b0), "r"(b1));
}

__device__ __forceinline__ void issue_tile_bf16(
    uint32_t stage_u,
    const __nv_bfloat16* __restrict__ A,
    const __nv_bfloat16* __restrict__ Bt,
    int kt, int t)
{
    uint32_t As_u = stage_u;
    uint32_t Bs_u = stage_u + 128*ABS_LD*2;
    #pragma unroll
    for (int j = 0; j < 2; j++) {
        int idx = t + 256*j;
        int row = idx >> 2, c8 = (idx & 3) << 3;
        cpa16(As_u + (uint32_t)(row*80 + c8*2), A + (size_t)row*HH + kt + c8);
    }
    #pragma unroll
    for (int j = 0; j < 2; j++) {
        int idx = t + 256*j;
        int n = idx >> 2, c8 = (idx & 3) << 3;
        cpa16(Bs_u + (uint32_t)(n*80 + c8*2), Bt + (size_t)n*HH + kt + c8);
    }
}

__device__ __forceinline__ void compute_tile_bf16(
    const __nv_bfloat16* __restrict__ As, const __nv_bfloat16* __restrict__ Bs,
    float (&acc)[2][8][4], int mwarp, int nwarp, int lq, int lp)
{
    #pragma unroll
    for (int s = 0; s < 2; s++) {
        int kb = s*16 + lp*2;
        unsigned a[2][4];
        #pragma unroll
        for (int mt = 0; mt < 2; mt++) {
            int r = mwarp*32 + mt*16 + lq;
            a[mt][0] = *(const unsigned*)(As + r*ABS_LD + kb);
            a[mt][1] = *(const unsigned*)(As + (r+8)*ABS_LD + kb);
            a[mt][2] = *(const unsigned*)(As + r*ABS_LD + kb + 8);
            a[mt][3] = *(const unsigned*)(As + (r+8)*ABS_LD + kb + 8);
        }
        #pragma unroll
        for (int nt = 0; nt < 8; nt++) {
            int n = nwarp*64 + nt*8 + lq;
            unsigned b0 = *(const unsigned*)(Bs + n*ABS_LD + kb);
            unsigned b1 = *(const unsigned*)(Bs + n*ABS_LD + kb + 8);
            mma_bf16(acc[0][nt], a[0], b0, b1);
            mma_bf16(acc[1][nt], a[1], b0, b1);
        }
    }
}

__device__ __forceinline__ void mma_core_bf16(
    const __nv_bfloat16* __restrict__ A,
    const __nv_bfloat16* __restrict__ Bt,
    float (&acc)[2][8][4], char* smp)
{
    const int t = threadIdx.x;
    const int lane = t & 31, wid = t >> 5;
    const int mwarp = wid & 3, nwarp = wid >> 2;
    const int lq = lane >> 2, lp = lane & 3;
    const uint32_t smp_u = smem_u32(smp);
    const int nsteps = HH / 32;   // 32

    issue_tile_bf16(smp_u, A, Bt, 0, t);
    CPA_COMMIT();
    issue_tile_bf16(smp_u + BSTAGE, A, Bt, 32, t);
    CPA_COMMIT();

    for (int i = 0; i < nsteps; i++) {
        CPA_WAIT1();
        __syncthreads();
        if (i + 2 < nsteps) {
            int s = (i + 2) % 3;
            issue_tile_bf16(smp_u + (uint32_t)s*BSTAGE, A, Bt, 32*(i+2), t);
        }
        CPA_COMMIT();
        int cs = i % 3;
        const __nv_bfloat16* As = (const __nv_bfloat16*)(smp + cs*BSTAGE);
        compute_tile_bf16(As, As + 128*ABS_LD, acc, mwarp, nwarp, lq, lp);
    }
}

// ---------------- embedding gather + environment copy (tf32-rounded into x) ----------------
__global__ void __launch_bounds__(256) k_embed(
    const int* __restrict__ ids, const float* __restrict__ emb,
    const float* __restrict__ env)
{
    int b = blockIdx.x, t = threadIdx.x;
    int id = ids[b];
    float* xr = g_x + (size_t)b*INSZ;
    for (int c = t; c < EE; c += 256)   xr[c]        = tf32f(emb[(size_t)id*EE + c]);
    for (int c = t; c < ENVD; c += 256) xr[2560 + c] = tf32f(env[(size_t)b*ENVD + c]);
}

// ---------------- h projections: g_hp/g_hc = h@W + b1 + b2 ----------------
__global__ void __launch_bounds__(256) k_hproj(
    const float* __restrict__ b1p, const float* __restrict__ b2p,
    const float* __restrict__ b1c, const float* __restrict__ b2c)
{
    extern __shared__ float smem[];
    float acc[2][8][4] = {};
    int n0 = blockIdx.x * 128;
    const float* W  = blockIdx.y ? g_Whc : g_Whp;
    const float* b1 = blockIdx.y ? b1c : b1p;
    const float* b2 = blockIdx.y ? b2c : b2p;
    float* out      = blockIdx.y ? g_hc : g_hp;

    mma_core_async(g_h0r, HH, W + n0, HH, 0, HH, 128, acc, smem);

    int t = threadIdx.x, lane = t & 31, wid = t >> 5;
    int mwarp = wid & 3, nwarp = wid >> 2, lq = lane >> 2, lp = lane & 3;
    #pragma unroll
    for (int mt = 0; mt < 2; mt++)
        #pragma unroll
        for (int nt = 0; nt < 8; nt++) {
            int r  = mwarp*32 + mt*16 + lq;
            int cb = n0 + nwarp*64 + nt*8 + lp*2;
            out[(size_t)r*HH + cb]       = acc[mt][nt][0] + b1[cb]   + b2[cb];
            out[(size_t)r*HH + cb+1]     = acc[mt][nt][1] + b1[cb+1] + b2[cb+1];
            out[(size_t)(r+8)*HH + cb]   = acc[mt][nt][2] + b1[cb]   + b2[cb];
            out[(size_t)(r+8)*HH + cb+1] = acc[mt][nt][3] + b1[cb+1] + b2[cb+1];
        }
}

// ---------------- fused attention: bf16 GEMM + tanh·wa partial-score epilogue ----------------
__global__ void __launch_bounds__(256) k_attn_score(
    const float* __restrict__ wa, int sel)
{
    extern __shared__ char smemc[];
    __shared__ float red[128][8];
    float acc[2][8][4] = {};
    int n0 = blockIdx.x * 128;
    int m0 = blockIdx.y * 128;

    const __nv_bfloat16* enc = sel ? g_encCb : g_encPb;
    const __nv_bfloat16* Wt  = sel ? g_WecT  : g_WepT;

    mma_core_bf16(enc + (size_t)m0*HH, Wt + (size_t)n0*HH, acc, smemc);

    const float* hp    = sel ? g_hc : g_hp;
    float*       spart = sel ? g_spC : g_spP;

    int t = threadIdx.x, lane = t & 31, wid = t >> 5;
    int mwarp = wid & 3, nwarp = wid >> 2, lq = lane >> 2, lp = lane & 3;

    float part[2][2] = {};
    #pragma unroll
    for (int mt = 0; mt < 2; mt++) {
        int r0 = mwarp*32 + mt*16 + lq;
        const float* hp0 = hp + (size_t)r0*HH;
        const float* hp8 = hp + (size_t)(r0+8)*HH;
        #pragma unroll
        for (int nt = 0; nt < 8; nt++) {
            int cb = n0 + nwarp*64 + nt*8 + lp*2;
            float w0 = wa[cb], w1 = wa[cb+1];
            part[mt][0] += tanhf(acc[mt][nt][0] + hp0[cb])   * w0
                         + tanhf(acc[mt][nt][1] + hp0[cb+1]) * w1;
            part[mt][1] += tanhf(acc[mt][nt][2] + hp8[cb])   * w0
                         + tanhf(acc[mt][nt][3] + hp8[cb+1]) * w1;
        }
    }
    int slot = nwarp*4 + lp;
    #pragma unroll
    for (int mt = 0; mt < 2; mt++) {
        red[mwarp*32 + mt*16 + lq][slot]     = part[mt][0];
        red[mwarp*32 + mt*16 + lq + 8][slot] = part[mt][1];
    }
    __syncthreads();
    if (t < 128) {
        float s = 0.f;
        #pragma unroll
        for (int p = 0; p < 8; p++) s += red[t][p];
        spart[(size_t)blockIdx.x*MATT + m0 + t] = s;
    }
}

// ---------------- softmax over S per batch row (sums 8 n-tile partials) ----------------
__global__ void __launch_bounds__(256) k_softmax(
    const float* __restrict__ b_a, int sel)
{
    const float* spart = sel ? g_spC : g_spP;
    float*       wout  = sel ? g_wC : g_wP;
    int b = blockIdx.x, s = threadIdx.x;
    float sc = *b_a;
    #pragma unroll
    for (int p = 0; p < 8; p++) sc += spart[(size_t)p*MATT + s*BB + b];

    __shared__ float sm[256];
    sm[s] = sc; __syncthreads();
    for (int o = 128; o > 0; o >>= 1) {
        if (s < o) sm[s] = fmaxf(sm[s], sm[s+o]);
        __syncthreads();
    }
    float mx = sm[0]; __syncthreads();
    float e = expf(sc - mx);
    sm[s] = e; __syncthreads();
    for (int o = 128; o > 0; o >>= 1) {
        if (s < o) sm[s] += sm[s+o];
        __syncthreads();
    }
    wout[s*BB + b] = e / sm[0];
}

// ---------------- context: ctx[b,:] = sum_s w[s,b]*enc[s,b,:] -> g_x (tf32-rounded) ----------------
__global__ void __launch_bounds__(256) k_context(
    const float* __restrict__ enc, int sel)
{
    const float* w  = sel ? g_wC : g_wP;
    const int   off = sel ? 1536 : 512;
    int b = blockIdx.x, t = threadIdx.x;
    __shared__ float ws[256];
    ws[t] = w[t*BB + b];
    __syncthreads();
    const float4* e4 = (const float4*)enc;
    float4 acc = make_float4(0.f, 0.f, 0.f, 0.f);
    #pragma unroll 8
    for (int s = 0; s < SS; s++) {
        float wv = ws[s];
        float4 v = e4[((size_t)(s*BB + b))*(HH/4) + t];
        acc.x = fmaf(wv, v.x, acc.x);
        acc.y = fmaf(wv, v.y, acc.y);
        acc.z = fmaf(wv, v.z, acc.z);
        acc.w = fmaf(wv, v.w, acc.w);
    }
    float4 rr;
    rr.x = tf32f(acc.x); rr.y = tf32f(acc.y); rr.z = tf32f(acc.z); rr.w = tf32f(acc.w);
    *(float4*)(g_x + (size_t)b*INSZ + off + t*4) = rr;
}

// ---------------- gates GEMM, K split into 5 chunks ----------------
__global__ void __launch_bounds__(256) k_gates_part()
{
    extern __shared__ float smem[];
    float acc[2][8][4] = {};
    int n0 = blockIdx.x * 128;
    int ch = blockIdx.y;
    if (ch < 4)
        mma_core_async(g_x, INSZ, g_Wih + n0, G4H, ch*864, (ch+1)*864, 128, acc, smem);
    else
        mma_core_async(g_h0r, HH, g_Whh + n0, G4H, 0, HH, 128, acc, smem);

    int t = threadIdx.x, lane = t & 31, wid = t >> 5;
    int mwarp = wid & 3, nwarp = wid >> 2, lq = lane >> 2, lp = lane & 3;
    float* dst = g_gpart + (size_t)ch*BB*G4H;
    #pragma unroll
    for (int mt = 0; mt < 2; mt++)
        #pragma unroll
        for (int nt = 0; nt < 8; nt++) {
            int r  = mwarp*32 + mt*16 + lq;
            int cb = n0 + nwarp*64 + nt*8 + lp*2;
            *(float2*)(dst + (size_t)r*G4H + cb)     = make_float2(acc[mt][nt][0], acc[mt][nt][1]);
            *(float2*)(dst + (size_t)(r+8)*G4H + cb) = make_float2(acc[mt][nt][2], acc[mt][nt][3]);
        }
}

__global__ void __launch_bounds__(256) k_gates_reduce(
    const float* __restrict__ b_ih, const float* __restrict__ b_hh)
{
    int idx = blockIdx.x*256 + threadIdx.x;
    int n = idx & (G4H-1);
    float s = b_ih[n] + b_hh[n];
    #pragma unroll
    for (int p = 0; p < 5; p++) s += g_gpart[(size_t)p*BB*G4H + idx];
    g_gates[idx] = s;
}

// ---------------- LSTM cell elementwise (double transcendentals: exact) ----------------
__global__ void __launch_bounds__(256) k_lstm(
    const float* __restrict__ c0, float* __restrict__ d_out, int write_out)
{
    int idx = blockIdx.x*256 + threadIdx.x;
    int b = idx >> 10, n = idx & 1023;
    const float* g = g_gates + (size_t)b*G4H;
    double gi = g[n], gf = g[1024+n], gg = g[2048+n], go = g[3072+n];
    double si = 1.0/(1.0 + exp(-gi));
    double sf = 1.0/(1.0 + exp(-gf));
    double so = 1.0/(1.0 + exp(-go));
    double c1 = sf * (double)c0[idx] + si * tanh(gg);
    double h1 = so * tanh(c1);
    float h1f = (float)h1;
    g_h1[idx] = tf32f(h1f);
    g_c1[idx] = (float)c1;
    if (write_out) {
        d_out[1280000 + idx] = h1f;
        d_out[1411072 + idx] = (float)c1;
    }
}

// ---------------- output GEMM, K split 2, N bounds ----------------
__global__ void __launch_bounds__(256) k_out_part()
{
    extern __shared__ float smem[];
    float acc[2][8][4] = {};
    int n0 = blockIdx.x * 128;
    int nvalid = VV - n0; if (nvalid > 128) nvalid = 128;
    int ks = blockIdx.y;
    mma_core_async(g_h1, HH, g_Wo + n0, VV, ks*512, (ks+1)*512, nvalid, acc, smem);

    int t = threadIdx.x, lane = t & 31, wid = t >> 5;
    int mwarp = wid & 3, nwarp = wid >> 2, lq = lane >> 2, lp = lane & 3;
    float* dst = g_opart + (size_t)ks*BB*VV;
    #pragma unroll
    for (int mt = 0; mt < 2; mt++)
        #pragma unroll
        for (int nt = 0; nt < 8; nt++) {
            int r  = mwarp*32 + mt*16 + lq;
            int cb = n0 + nwarp*64 + nt*8 + lp*2;
            if (cb + 1 < VV) {
                *(float2*)(dst + (size_t)r*VV + cb)     = make_float2(acc[mt][nt][0], acc[mt][nt][1]);
                *(float2*)(dst + (size_t)(r+8)*VV + cb) = make_float2(acc[mt][nt][2], acc[mt][nt][3]);
            }
        }
}

__global__ void __launch_bounds__(256) k_out_reduce(
    const float* __restrict__ b_out, float* __restrict__ out)
{
    int idx = blockIdx.x*256 + threadIdx.x;
    if (idx < BB*VV) {
        int n = idx % VV;
        out[idx] = g_opart[idx] + g_opart[(size_t)BB*VV + idx] + b_out[n];
    }
}

// ---------------- launch ----------------
extern "C" void kernel_launch(void* const* d_in, const int* in_sizes, int n_in,
                              void* d_out, int out_size)
{
    const int*   ids  = (const int*)d_in[0];
    const float* prev = (const float*)d_in[1];
    const float* encc = (const float*)d_in[2];
    const float* env  = (const float*)d_in[3];
    const float* h0   = (const float*)d_in[4];
    const float* c0   = (const float*)d_in[5];
    const float* emb  = (const float*)d_in[6];
    const float* W_hp = (const float*)d_in[7];
    const float* b_hp = (const float*)d_in[8];
    const float* W_ep = (const float*)d_in[9];
    const float* b_ep = (const float*)d_in[10];
    const float* w_ap = (const float*)d_in[11];
    const float* b_ap = (const float*)d_in[12];
    const float* W_hc = (const float*)d_in[13];
    const float* b_hc = (const float*)d_in[14];
    const float* W_ec = (const float*)d_in[15];
    const float* b_ec = (const float*)d_in[16];
    const float* w_ac = (const float*)d_in[17];
    const float* b_ac = (const float*)d_in[18];

    const float* W_ih = (const float*)d_in[19];
    const float* W_hh; const float* b_ih; const float* b_hh;
    if (in_sizes[20] == 1024*4096) {
        W_hh = (const float*)d_in[20];
        b_ih = (const float*)d_in[21];
        b_hh = (const float*)d_in[22];
    } else {
        b_ih = (const float*)d_in[20];
        W_hh = (const float*)d_in[21];
        b_hh = (const float*)d_in[22];
    }
    const float* W_out = (const float*)d_in[23];
    const float* b_out = (const float*)d_in[24];

    float* out = (float*)d_out;
    int write_state = (out_size >= 1542144) ? 1 : 0;

    cudaFuncSetAttribute(k_hproj,      cudaFuncAttributeMaxDynamicSharedMemorySize, SMEM_BYTES);
    cudaFuncSetAttribute(k_attn_score, cudaFuncAttributeMaxDynamicSharedMemorySize, ATTN_SMEM);
    cudaFuncSetAttribute(k_gates_part, cudaFuncAttributeMaxDynamicSharedMemorySize, SMEM_BYTES);
    cudaFuncSetAttribute(k_out_part,   cudaFuncAttributeMaxDynamicSharedMemorySize, SMEM_BYTES);

    // 0. operand prep: bf16 for attention, tf32 for the rest
    k_enc_bf16<<<32768, 256>>>(prev, 0);
    k_enc_bf16<<<32768, 256>>>(encc, 1);
    k_wT<<<dim3(32,32), 256>>>(W_ep, 0);
    k_wT<<<dim3(32,32), 256>>>(W_ec, 1);
    k_round<<<(262144+255)/256, 256>>>(W_hp,  0, 262144);
    k_round<<<(262144+255)/256, 256>>>(W_hc,  1, 262144);
    k_round<<<(3538944+255)/256, 256>>>(W_ih, 2, 3538944);
    k_round<<<(1048576+255)/256, 256>>>(W_hh, 3, 1048576);
    k_round<<<(2560000+255)/256, 256>>>(W_out,4, 2560000);
    k_round<<<(32768+255)/256, 256>>>(h0,     5, 32768);

    k_embed<<<BB, 256>>>(ids, emb, env);
    k_hproj<<<dim3(8,2), 256, SMEM_BYTES>>>(b_hp, b_ep, b_hc, b_ec);
    k_attn_score<<<dim3(8,256), 256, ATTN_SMEM>>>(w_ap, 0);
    k_attn_score<<<dim3(8,256), 256, ATTN_SMEM>>>(w_ac, 1);
    k_softmax<<<BB, 256>>>(b_ap, 0);
    k_softmax<<<BB, 256>>>(b_ac, 1);
    k_context<<<BB, 256>>>(prev, 0);
    k_context<<<BB, 256>>>(encc, 1);
    k_gates_part<<<dim3(32,5), 256, SMEM_BYTES>>>();
    k_gates_reduce<<<(BB*G4H)/256, 256>>>(b_ih, b_hh);
    k_lstm<<<(BB*HH)/256, 256>>>(c0, out, write_state);
    k_out_part<<<dim3(79,2), 256, SMEM_BYTES>>>();
    k_out_reduce<<<(BB*VV + 255)/256, 256>>>(b_out, out);
}

// round 15
// speedup vs baseline: 1.5032x; 1.0819x over previous
#include <cuda_runtime.h>
#include <cuda_bf16.h>
#include <cstdint>
#include <math.h>

// Problem constants
#define BB 128
#define SS 256
#define HH 1024
#define EE 512
#define ENVD 896
#define VV 10000
#define INSZ 3456          // E + H + H + ENV
#define MATT (SS*BB)       // 32768
#define G4H 4096

// fp32 -> tf32 (rna) kept in a float container.
__device__ __forceinline__ float tf32f(float x) {
    unsigned r;
    asm("cvt.rna.tf32.f32 %0, %1;" : "=r"(r) : "f"(x));
    return __uint_as_float(r);
}
__device__ __forceinline__ unsigned short bfbits(float x) {
    __nv_bfloat16 h = __float2bfloat16_rn(x);
    return *reinterpret_cast<unsigned short*>(&h);
}
__device__ __forceinline__ uint32_t smem_u32(const void* p) {
    uint32_t a;
    asm("{ .reg .u64 t; cvta.to.shared.u64 t, %1; cvt.u32.u64 %0, t; }" : "=r"(a) : "l"(p));
    return a;
}

// ---------------- scratch (device globals; DEVICE-CODE-ONLY references) ----------------
__device__ float g_x[BB*INSZ];
__device__ float g_hp[BB*HH];
__device__ float g_hc[BB*HH];
__device__ float g_spP[8*MATT];
__device__ float g_spC[8*MATT];
__device__ float g_wP[MATT];
__device__ float g_wC[MATT];
__device__ float g_gpart[5*BB*G4H];
__device__ float g_gates[BB*G4H];
__device__ float g_opart[2*BB*VV];
__device__ float g_h1[BB*HH];
__device__ float g_c1[BB*HH];
// tf32-pre-rounded operands (gates / out / hproj)
__device__ float g_Whp[HH*HH];
__device__ float g_Whc[HH*HH];
__device__ float g_Wih[INSZ*G4H];
__device__ float g_Whh[HH*G4H];
__device__ float g_Wo[HH*VV];
__device__ float g_h0r[BB*HH];
// bf16 operands for attention GEMM
__device__ __nv_bfloat16 g_encPb[(size_t)MATT*HH];
__device__ __nv_bfloat16 g_encCb[(size_t)MATT*HH];
__device__ __nv_bfloat16 g_WepT[HH*HH];   // transposed [n][k]
__device__ __nv_bfloat16 g_WecT[HH*HH];

// ---------------- prep kernels ----------------
__global__ void __launch_bounds__(256) k_round(const float* __restrict__ src, int which, int n4)
{
    int i = blockIdx.x*256 + threadIdx.x;
    if (i >= n4) return;
    float* dst;
    switch (which) {
        case 0: dst = g_Whp; break;
        case 1: dst = g_Whc; break;
        case 2: dst = g_Wih; break;
        case 3: dst = g_Whh; break;
        case 4: dst = g_Wo;  break;
        default: dst = g_h0r; break;
    }
    float4 v = ((const float4*)src)[i];
    float4 w;
    w.x = tf32f(v.x); w.y = tf32f(v.y); w.z = tf32f(v.z); w.w = tf32f(v.w);
    ((float4*)dst)[i] = w;
}

__global__ void __launch_bounds__(256) k_enc_bf16(
    const float* __restrict__ srcP, const float* __restrict__ srcC)
{
    size_t i = (size_t)blockIdx.x*256 + threadIdx.x;   // float4 index
    const float* src = blockIdx.y ? srcC : srcP;
    __nv_bfloat16* dst = blockIdx.y ? g_encCb : g_encPb;
    float4 v = ((const float4*)src)[i];
    uint2 o;
    o.x = (uint32_t)bfbits(v.x) | ((uint32_t)bfbits(v.y) << 16);
    o.y = (uint32_t)bfbits(v.z) | ((uint32_t)bfbits(v.w) << 16);
    ((uint2*)dst)[i] = o;
}

// transpose W [k][n] fp32 -> Wt [n][k] bf16 (32x32 tiles via smem)
__global__ void __launch_bounds__(256) k_wT(
    const float* __restrict__ Wp, const float* __restrict__ Wc)
{
    __shared__ float tile[32][33];
    const float* W = blockIdx.z ? Wc : Wp;
    int n0 = blockIdx.x*32, k0 = blockIdx.y*32;
    int tx = threadIdx.x & 31, ty = threadIdx.x >> 5;
    #pragma unroll
    for (int i = 0; i < 32; i += 8)
        tile[ty+i][tx] = W[(size_t)(k0+ty+i)*HH + n0+tx];
    __syncthreads();
    __nv_bfloat16* Wt = blockIdx.z ? g_WecT : g_WepT;
    #pragma unroll
    for (int i = 0; i < 32; i += 8)
        Wt[(size_t)(n0+ty+i)*HH + k0+tx] = __float2bfloat16_rn(tile[tx][ty+i]);
}

// ---------------- cp.async primitives ----------------
__device__ __forceinline__ void cpa16(uint32_t dst, const void* src) {
    asm volatile("cp.async.cg.shared.global [%0], [%1], 16;" :: "r"(dst), "l"(src));
}
__device__ __forceinline__ void cpa16z(uint32_t dst, const void* src, int bytes) {
    asm volatile("cp.async.cg.shared.global [%0], [%1], 16, %2;" :: "r"(dst), "l"(src), "r"(bytes));
}
#define CPA_COMMIT() asm volatile("cp.async.commit_group;" ::: "memory")
#define CPA_WAIT1()  asm volatile("cp.async.wait_group 1;" ::: "memory")

// ---------------- tf32 mma.sync GEMM core, 3-stage cp.async (hproj/gates/out) ----------------
#define AS_LD 36
#define BS_LD 136
#define STAGE_F (128*AS_LD + 32*BS_LD)
#define SMEM_BYTES (3*STAGE_F*4)

__device__ __forceinline__ void mma_tf32(float* c, const unsigned* a, unsigned b0, unsigned b1) {
    asm volatile(
        "mma.sync.aligned.m16n8k8.row.col.f32.tf32.tf32.f32 "
        "{%0,%1,%2,%3},{%4,%5,%6,%7},{%8,%9},{%0,%1,%2,%3};"
        : "+f"(c[0]), "+f"(c[1]), "+f"(c[2]), "+f"(c[3])
        : "r"(a[0]), "r"(a[1]), "r"(a[2]), "r"(a[3]), "r"(b0), "r"(b1));
}

__device__ __forceinline__ void issue_tile_async(
    uint32_t stage_u,
    const float* __restrict__ A, int lda,
    const float* __restrict__ Wn, int ldw,
    int kt, int nvalid, int t)
{
    uint32_t As_u = stage_u;
    uint32_t Bs_u = stage_u + 128*AS_LD*4;
    #pragma unroll
    for (int j = 0; j < 4; j++) {
        int idx = t + 256*j;
        int row = idx >> 3, cq = (idx & 7) << 2;
        cpa16(As_u + (uint32_t)(row*AS_LD + cq)*4, A + (size_t)row*lda + kt + cq);
    }
    #pragma unroll
    for (int j = 0; j < 4; j++) {
        int idx = t + 256*j;
        int kr = idx >> 5, nq = (idx & 31) << 2;
        const float* src = Wn + (size_t)(kt + kr)*ldw + nq;
        uint32_t dst = Bs_u + (uint32_t)(kr*BS_LD + nq)*4;
        if (nvalid >= 128) {
            cpa16(dst, src);
        } else {
            int rem = nvalid - nq;
            int bytes = rem >= 4 ? 16 : (rem > 0 ? rem*4 : 0);
            cpa16z(dst, rem > 0 ? src : Wn, bytes);
        }
    }
}

__device__ __forceinline__ void compute_tile(
    const float* __restrict__ As, const float* __restrict__ Bs,
    float (&acc)[2][8][4], int mwarp, int nwarp, int lq, int lp)
{
    #pragma unroll
    for (int k8 = 0; k8 < 32; k8 += 8) {
        unsigned a[2][4];
        #pragma unroll
        for (int mt = 0; mt < 2; mt++) {
            int r = mwarp*32 + mt*16 + lq;
            int c = k8 + lp;
            a[mt][0] = __float_as_uint(As[r*AS_LD + c]);
            a[mt][1] = __float_as_uint(As[(r+8)*AS_LD + c]);
            a[mt][2] = __float_as_uint(As[r*AS_LD + c + 4]);
            a[mt][3] = __float_as_uint(As[(r+8)*AS_LD + c + 4]);
        }
        #pragma unroll
        for (int nt = 0; nt < 8; nt++) {
            int n  = nwarp*64 + nt*8 + lq;
            int kb = k8 + lp;
            unsigned b0 = __float_as_uint(Bs[kb*BS_LD + n]);
            unsigned b1 = __float_as_uint(Bs[(kb+4)*BS_LD + n]);
            mma_tf32(acc[0][nt], a[0], b0, b1);
            mma_tf32(acc[1][nt], a[1], b0, b1);
        }
    }
}

__device__ __forceinline__ void mma_core_async(
    const float* __restrict__ A, int lda,
    const float* __restrict__ Wn, int ldw,
    int k0, int k1, int nvalid,
    float (&acc)[2][8][4], float* smp)
{
    const int t = threadIdx.x;
    const int lane = t & 31, wid = t >> 5;
    const int mwarp = wid & 3, nwarp = wid >> 2;
    const int lq = lane >> 2, lp = lane & 3;
    const uint32_t smp_u = smem_u32(smp);
    const int nsteps = (k1 - k0) >> 5;

    issue_tile_async(smp_u, A, lda, Wn, ldw, k0, nvalid, t);
    CPA_COMMIT();
    if (nsteps > 1)
        issue_tile_async(smp_u + STAGE_F*4, A, lda, Wn, ldw, k0 + 32, nvalid, t);
    CPA_COMMIT();

    for (int i = 0; i < nsteps; i++) {
        CPA_WAIT1();
        __syncthreads();
        if (i + 2 < nsteps) {
            int s = (i + 2) % 3;
            issue_tile_async(smp_u + (uint32_t)s*STAGE_F*4, A, lda, Wn, ldw,
                             k0 + 32*(i+2), nvalid, t);
        }
        CPA_COMMIT();
        int cs = i % 3;
        compute_tile(smp + cs*STAGE_F, smp + cs*STAGE_F + 128*AS_LD,
                     acc, mwarp, nwarp, lq, lp);
    }
}

// ---------------- bf16 mma.sync GEMM core, ldmatrix fragments, 3-stage cp.async ----------------
#define ABS_LD 40                            // bf16 elems/row (80B, conflict-free)
#define BSTAGE (2*128*ABS_LD*2)              // 20480 bytes
#define ATTN_SMEM (3*BSTAGE)                 // 61440

__device__ __forceinline__ void mma_bf16(float* c, const unsigned* a, unsigned b0, unsigned b1) {
    asm volatile(
        "mma.sync.aligned.m16n8k16.row.col.f32.bf16.bf16.f32 "
        "{%0,%1,%2,%3},{%4,%5,%6,%7},{%8,%9},{%0,%1,%2,%3};"
        : "+f"(c[0]), "+f"(c[1]), "+f"(c[2]), "+f"(c[3])
        : "r"(a[0]), "r"(a[1]), "r"(a[2]), "r"(a[3]), "r"(b0), "r"(b1));
}
__device__ __forceinline__ void ldsm4(uint32_t a, unsigned &r0, unsigned &r1, unsigned &r2, unsigned &r3) {
    asm volatile("ldmatrix.sync.aligned.m8n8.x4.shared.b16 {%0,%1,%2,%3}, [%4];"
        : "=r"(r0), "=r"(r1), "=r"(r2), "=r"(r3) : "r"(a));
}

__device__ __forceinline__ void issue_tile_bf16(
    uint32_t stage_u,
    const __nv_bfloat16* __restrict__ A,
    const __nv_bfloat16* __restrict__ Bt,
    int kt, int t)
{
    uint32_t As_u = stage_u;
    uint32_t Bs_u = stage_u + 128*ABS_LD*2;
    #pragma unroll
    for (int j = 0; j < 2; j++) {
        int idx = t + 256*j;
        int row = idx >> 2, c8 = (idx & 3) << 3;
        cpa16(As_u + (uint32_t)(row*80 + c8*2), A + (size_t)row*HH + kt + c8);
    }
    #pragma unroll
    for (int j = 0; j < 2; j++) {
        int idx = t + 256*j;
        int n = idx >> 2, c8 = (idx & 3) << 3;
        cpa16(Bs_u + (uint32_t)(n*80 + c8*2), Bt + (size_t)n*HH + kt + c8);
    }
}

// ldmatrix-based fragment loads.
// A x4 for (mt,s): mats {m0-7/k0-7, m8-15/k0-7, m0-7/k8-15, m8-15/k8-15} -> a0..a3.
// Lane L sources row base_m + ((L>>3)&1)*8 + (L&7), col s*16 + (L>>4)*8.
// B x4 for (pair p, s): mats {n(2p)/k0-7, n(2p)/k8-15, n(2p+1)/k0-7, n(2p+1)/k8-15}.
// Lane L sources row n0 + ((L>>4)&1)*8 + (L&7), col s*16 + ((L>>3)&1)*8.
__device__ __forceinline__ void compute_tile_bf16(
    uint32_t As_u, uint32_t Bs_u,
    float (&acc)[2][8][4], uint32_t a_off, uint32_t b_off)
{
    #pragma unroll
    for (int s = 0; s < 2; s++) {
        unsigned a0[4], a1[4];
        ldsm4(As_u + a_off + (uint32_t)(s*16)*2,                 a0[0], a0[1], a0[2], a0[3]);
        ldsm4(As_u + a_off + (uint32_t)(16*ABS_LD + s*16)*2,     a1[0], a1[1], a1[2], a1[3]);
        unsigned b[8][2];
        #pragma unroll
        for (int p = 0; p < 4; p++) {
            ldsm4(Bs_u + b_off + (uint32_t)(p*16*ABS_LD + s*16)*2,
                  b[2*p][0], b[2*p][1], b[2*p+1][0], b[2*p+1][1]);
        }
        #pragma unroll
        for (int nt = 0; nt < 8; nt++) {
            mma_bf16(acc[0][nt], a0, b[nt][0], b[nt][1]);
            mma_bf16(acc[1][nt], a1, b[nt][0], b[nt][1]);
        }
    }
}

__device__ __forceinline__ void mma_core_bf16(
    const __nv_bfloat16* __restrict__ A,
    const __nv_bfloat16* __restrict__ Bt,
    float (&acc)[2][8][4], char* smp)
{
    const int t = threadIdx.x;
    const int lane = t & 31, wid = t >> 5;
    const int mwarp = wid & 3, nwarp = wid >> 2;
    const uint32_t smp_u = smem_u32(smp);
    const int nsteps = HH / 32;   // 32

    // per-lane ldmatrix source offsets (bytes)
    const int arow = mwarp*32 + ((lane>>3)&1)*8 + (lane&7);
    const int acol = (lane>>4)*8;
    const uint32_t a_off = (uint32_t)(arow*ABS_LD + acol)*2;
    const int brow = nwarp*64 + ((lane>>4)&1)*8 + (lane&7);
    const int bcol = ((lane>>3)&1)*8;
    const uint32_t b_off = (uint32_t)(brow*ABS_LD + bcol)*2;

    issue_tile_bf16(smp_u, A, Bt, 0, t);
    CPA_COMMIT();
    issue_tile_bf16(smp_u + BSTAGE, A, Bt, 32, t);
    CPA_COMMIT();

    for (int i = 0; i < nsteps; i++) {
        CPA_WAIT1();
        __syncthreads();
        if (i + 2 < nsteps) {
            int s = (i + 2) % 3;
            issue_tile_bf16(smp_u + (uint32_t)s*BSTAGE, A, Bt, 32*(i+2), t);
        }
        CPA_COMMIT();
        int cs = i % 3;
        uint32_t As_u = smp_u + (uint32_t)cs*BSTAGE;
        compute_tile_bf16(As_u, As_u + 128*ABS_LD*2, acc, a_off, b_off);
    }
}

// ---------------- embedding gather + environment copy (tf32-rounded into x) ----------------
__global__ void __launch_bounds__(256) k_embed(
    const int* __restrict__ ids, const float* __restrict__ emb,
    const float* __restrict__ env)
{
    int b = blockIdx.x, t = threadIdx.x;
    int id = ids[b];
    float* xr = g_x + (size_t)b*INSZ;
    for (int c = t; c < EE; c += 256)   xr[c]        = tf32f(emb[(size_t)id*EE + c]);
    for (int c = t; c < ENVD; c += 256) xr[2560 + c] = tf32f(env[(size_t)b*ENVD + c]);
}

// ---------------- h projections: g_hp/g_hc = h@W + b1 + b2 ----------------
__global__ void __launch_bounds__(256) k_hproj(
    const float* __restrict__ b1p, const float* __restrict__ b2p,
    const float* __restrict__ b1c, const float* __restrict__ b2c)
{
    extern __shared__ float smem[];
    float acc[2][8][4] = {};
    int n0 = blockIdx.x * 128;
    const float* W  = blockIdx.y ? g_Whc : g_Whp;
    const float* b1 = blockIdx.y ? b1c : b1p;
    const float* b2 = blockIdx.y ? b2c : b2p;
    float* out      = blockIdx.y ? g_hc : g_hp;

    mma_core_async(g_h0r, HH, W + n0, HH, 0, HH, 128, acc, smem);

    int t = threadIdx.x, lane = t & 31, wid = t >> 5;
    int mwarp = wid & 3, nwarp = wid >> 2, lq = lane >> 2, lp = lane & 3;
    #pragma unroll
    for (int mt = 0; mt < 2; mt++)
        #pragma unroll
        for (int nt = 0; nt < 8; nt++) {
            int r  = mwarp*32 + mt*16 + lq;
            int cb = n0 + nwarp*64 + nt*8 + lp*2;
            out[(size_t)r*HH + cb]       = acc[mt][nt][0] + b1[cb]   + b2[cb];
            out[(size_t)r*HH + cb+1]     = acc[mt][nt][1] + b1[cb+1] + b2[cb+1];
            out[(size_t)(r+8)*HH + cb]   = acc[mt][nt][2] + b1[cb]   + b2[cb];
            out[(size_t)(r+8)*HH + cb+1] = acc[mt][nt][3] + b1[cb+1] + b2[cb+1];
        }
}

// ---------------- fused attention: bf16 GEMM (ldmatrix) + tanh·wa epilogue ----------------
// grid (8, 256, 2): z selects prev/cur attention.
__global__ void __launch_bounds__(256) k_attn_score(
    const float* __restrict__ waP, const float* __restrict__ waC)
{
    extern __shared__ char smemc[];
    __shared__ float red[128][8];
    float acc[2][8][4] = {};
    int n0 = blockIdx.x * 128;
    int m0 = blockIdx.y * 128;
    int sel = blockIdx.z;

    const __nv_bfloat16* enc = sel ? g_encCb : g_encPb;
    const __nv_bfloat16* Wt  = sel ? g_WecT  : g_WepT;
    const float* wa          = sel ? waC : waP;

    mma_core_bf16(enc + (size_t)m0*HH, Wt + (size_t)n0*HH, acc, smemc);

    const float* hp    = sel ? g_hc : g_hp;
    float*       spart = sel ? g_spC : g_spP;

    int t = threadIdx.x, lane = t & 31, wid = t >> 5;
    int mwarp = wid & 3, nwarp = wid >> 2, lq = lane >> 2, lp = lane & 3;

    float part[2][2] = {};
    #pragma unroll
    for (int mt = 0; mt < 2; mt++) {
        int r0 = mwarp*32 + mt*16 + lq;
        const float* hp0 = hp + (size_t)r0*HH;
        const float* hp8 = hp + (size_t)(r0+8)*HH;
        #pragma unroll
        for (int nt = 0; nt < 8; nt++) {
            int cb = n0 + nwarp*64 + nt*8 + lp*2;
            float w0 = wa[cb], w1 = wa[cb+1];
            part[mt][0] += tanhf(acc[mt][nt][0] + hp0[cb])   * w0
                         + tanhf(acc[mt][nt][1] + hp0[cb+1]) * w1;
            part[mt][1] += tanhf(acc[mt][nt][2] + hp8[cb])   * w0
                         + tanhf(acc[mt][nt][3] + hp8[cb+1]) * w1;
        }
    }
    int slot = nwarp*4 + lp;
    #pragma unroll
    for (int mt = 0; mt < 2; mt++) {
        red[mwarp*32 + mt*16 + lq][slot]     = part[mt][0];
        red[mwarp*32 + mt*16 + lq + 8][slot] = part[mt][1];
    }
    __syncthreads();
    if (t < 128) {
        float s = 0.f;
        #pragma unroll
        for (int p = 0; p < 8; p++) s += red[t][p];
        spart[(size_t)blockIdx.x*MATT + m0 + t] = s;
    }
}

// ---------------- softmax over S per batch row (sums 8 n-tile partials) ----------------
__global__ void __launch_bounds__(256) k_softmax(
    const float* __restrict__ b_a, int sel)
{
    const float* spart = sel ? g_spC : g_spP;
    float*       wout  = sel ? g_wC : g_wP;
    int b = blockIdx.x, s = threadIdx.x;
    float sc = *b_a;
    #pragma unroll
    for (int p = 0; p < 8; p++) sc += spart[(size_t)p*MATT + s*BB + b];

    __shared__ float sm[256];
    sm[s] = sc; __syncthreads();
    for (int o = 128; o > 0; o >>= 1) {
        if (s < o) sm[s] = fmaxf(sm[s], sm[s+o]);
        __syncthreads();
    }
    float mx = sm[0]; __syncthreads();
    float e = expf(sc - mx);
    sm[s] = e; __syncthreads();
    for (int o = 128; o > 0; o >>= 1) {
        if (s < o) sm[s] += sm[s+o];
        __syncthreads();
    }
    wout[s*BB + b] = e / sm[0];
}

// ---------------- context: ctx[b,:] = sum_s w[s,b]*enc[s,b,:] -> g_x (tf32-rounded) ----------------
__global__ void __launch_bounds__(256) k_context(
    const float* __restrict__ enc, int sel)
{
    const float* w  = sel ? g_wC : g_wP;
    const int   off = sel ? 1536 : 512;
    int b = blockIdx.x, t = threadIdx.x;
    __shared__ float ws[256];
    ws[t] = w[t*BB + b];
    __syncthreads();
    const float4* e4 = (const float4*)enc;
    float4 acc = make_float4(0.f, 0.f, 0.f, 0.f);
    #pragma unroll 8
    for (int s = 0; s < SS; s++) {
        float wv = ws[s];
        float4 v = e4[((size_t)(s*BB + b))*(HH/4) + t];
        acc.x = fmaf(wv, v.x, acc.x);
        acc.y = fmaf(wv, v.y, acc.y);
        acc.z = fmaf(wv, v.z, acc.z);
        acc.w = fmaf(wv, v.w, acc.w);
    }
    float4 rr;
    rr.x = tf32f(acc.x); rr.y = tf32f(acc.y); rr.z = tf32f(acc.z); rr.w = tf32f(acc.w);
    *(float4*)(g_x + (size_t)b*INSZ + off + t*4) = rr;
}

// ---------------- gates GEMM, K split into 5 chunks ----------------
__global__ void __launch_bounds__(256) k_gates_part()
{
    extern __shared__ float smem[];
    float acc[2][8][4] = {};
    int n0 = blockIdx.x * 128;
    int ch = blockIdx.y;
    if (ch < 4)
        mma_core_async(g_x, INSZ, g_Wih + n0, G4H, ch*864, (ch+1)*864, 128, acc, smem);
    else
        mma_core_async(g_h0r, HH, g_Whh + n0, G4H, 0, HH, 128, acc, smem);

    int t = threadIdx.x, lane = t & 31, wid = t >> 5;
    int mwarp = wid & 3, nwarp = wid >> 2, lq = lane >> 2, lp = lane & 3;
    float* dst = g_gpart + (size_t)ch*BB*G4H;
    #pragma unroll
    for (int mt = 0; mt < 2; mt++)
        #pragma unroll
        for (int nt = 0; nt < 8; nt++) {
            int r  = mwarp*32 + mt*16 + lq;
            int cb = n0 + nwarp*64 + nt*8 + lp*2;
            *(float2*)(dst + (size_t)r*G4H + cb)     = make_float2(acc[mt][nt][0], acc[mt][nt][1]);
            *(float2*)(dst + (size_t)(r+8)*G4H + cb) = make_float2(acc[mt][nt][2], acc[mt][nt][3]);
        }
}

__global__ void __launch_bounds__(256) k_gates_reduce(
    const float* __restrict__ b_ih, const float* __restrict__ b_hh)
{
    int idx = blockIdx.x*256 + threadIdx.x;
    int n = idx & (G4H-1);
    float s = b_ih[n] + b_hh[n];
    #pragma unroll
    for (int p = 0; p < 5; p++) s += g_gpart[(size_t)p*BB*G4H + idx];
    g_gates[idx] = s;
}

// ---------------- LSTM cell elementwise (double transcendentals: exact) ----------------
__global__ void __launch_bounds__(256) k_lstm(
    const float* __restrict__ c0, float* __restrict__ d_out, int write_out)
{
    int idx = blockIdx.x*256 + threadIdx.x;
    int b = idx >> 10, n = idx & 1023;
    const float* g = g_gates + (size_t)b*G4H;
    double gi = g[n], gf = g[1024+n], gg = g[2048+n], go = g[3072+n];
    double si = 1.0/(1.0 + exp(-gi));
    double sf = 1.0/(1.0 + exp(-gf));
    double so = 1.0/(1.0 + exp(-go));
    double c1 = sf * (double)c0[idx] + si * tanh(gg);
    double h1 = so * tanh(c1);
    float h1f = (float)h1;
    g_h1[idx] = tf32f(h1f);
    g_c1[idx] = (float)c1;
    if (write_out) {
        d_out[1280000 + idx] = h1f;
        d_out[1411072 + idx] = (float)c1;
    }
}

// ---------------- output GEMM, K split 2, N bounds ----------------
__global__ void __launch_bounds__(256) k_out_part()
{
    extern __shared__ float smem[];
    float acc[2][8][4] = {};
    int n0 = blockIdx.x * 128;
    int nvalid = VV - n0; if (nvalid > 128) nvalid = 128;
    int ks = blockIdx.y;
    mma_core_async(g_h1, HH, g_Wo + n0, VV, ks*512, (ks+1)*512, nvalid, acc, smem);

    int t = threadIdx.x, lane = t & 31, wid = t >> 5;
    int mwarp = wid & 3, nwarp = wid >> 2, lq = lane >> 2, lp = lane & 3;
    float* dst = g_opart + (size_t)ks*BB*VV;
    #pragma unroll
    for (int mt = 0; mt < 2; mt++)
        #pragma unroll
        for (int nt = 0; nt < 8; nt++) {
            int r  = mwarp*32 + mt*16 + lq;
            int cb = n0 + nwarp*64 + nt*8 + lp*2;
            if (cb + 1 < VV) {
                *(float2*)(dst + (size_t)r*VV + cb)     = make_float2(acc[mt][nt][0], acc[mt][nt][1]);
                *(float2*)(dst + (size_t)(r+8)*VV + cb) = make_float2(acc[mt][nt][2], acc[mt][nt][3]);
            }
        }
}

__global__ void __launch_bounds__(256) k_out_reduce(
    const float* __restrict__ b_out, float* __restrict__ out)
{
    int idx = blockIdx.x*256 + threadIdx.x;
    if (idx < BB*VV) {
        int n = idx % VV;
        out[idx] = g_opart[idx] + g_opart[(size_t)BB*VV + idx] + b_out[n];
    }
}

// ---------------- launch ----------------
extern "C" void kernel_launch(void* const* d_in, const int* in_sizes, int n_in,
                              void* d_out, int out_size)
{
    const int*   ids  = (const int*)d_in[0];
    const float* prev = (const float*)d_in[1];
    const float* encc = (const float*)d_in[2];
    const float* env  = (const float*)d_in[3];
    const float* h0   = (const float*)d_in[4];
    const float* c0   = (const float*)d_in[5];
    const float* emb  = (const float*)d_in[6];
    const float* W_hp = (const float*)d_in[7];
    const float* b_hp = (const float*)d_in[8];
    const float* W_ep = (const float*)d_in[9];
    const float* b_ep = (const float*)d_in[10];
    const float* w_ap = (const float*)d_in[11];
    const float* b_ap = (const float*)d_in[12];
    const float* W_hc = (const float*)d_in[13];
    const float* b_hc = (const float*)d_in[14];
    const float* W_ec = (const float*)d_in[15];
    const float* b_ec = (const float*)d_in[16];
    const float* w_ac = (const float*)d_in[17];
    const float* b_ac = (const float*)d_in[18];

    const float* W_ih = (const float*)d_in[19];
    const float* W_hh; const float* b_ih; const float* b_hh;
    if (in_sizes[20] == 1024*4096) {
        W_hh = (const float*)d_in[20];
        b_ih = (const float*)d_in[21];
        b_hh = (const float*)d_in[22];
    } else {
        b_ih = (const float*)d_in[20];
        W_hh = (const float*)d_in[21];
        b_hh = (const float*)d_in[22];
    }
    const float* W_out = (const float*)d_in[23];
    const float* b_out = (const float*)d_in[24];

    float* out = (float*)d_out;
    int write_state = (out_size >= 1542144) ? 1 : 0;

    cudaFuncSetAttribute(k_hproj,      cudaFuncAttributeMaxDynamicSharedMemorySize, SMEM_BYTES);
    cudaFuncSetAttribute(k_attn_score, cudaFuncAttributeMaxDynamicSharedMemorySize, ATTN_SMEM);
    cudaFuncSetAttribute(k_gates_part, cudaFuncAttributeMaxDynamicSharedMemorySize, SMEM_BYTES);
    cudaFuncSetAttribute(k_out_part,   cudaFuncAttributeMaxDynamicSharedMemorySize, SMEM_BYTES);

    // 0. operand prep: bf16 for attention, tf32 for the rest
    k_enc_bf16<<<dim3(32768,2), 256>>>(prev, encc);
    k_wT<<<dim3(32,32,2), 256>>>(W_ep, W_ec);
    k_round<<<(262144+255)/256, 256>>>(W_hp,  0, 262144);
    k_round<<<(262144+255)/256, 256>>>(W_hc,  1, 262144);
    k_round<<<(3538944+255)/256, 256>>>(W_ih, 2, 3538944);
    k_round<<<(1048576+255)/256, 256>>>(W_hh, 3, 1048576);
    k_round<<<(2560000+255)/256, 256>>>(W_out,4, 2560000);
    k_round<<<(32768+255)/256, 256>>>(h0,     5, 32768);

    k_embed<<<BB, 256>>>(ids, emb, env);
    k_hproj<<<dim3(8,2), 256, SMEM_BYTES>>>(b_hp, b_ep, b_hc, b_ec);
    k_attn_score<<<dim3(8,256,2), 256, ATTN_SMEM>>>(w_ap, w_ac);
    k_softmax<<<BB, 256>>>(b_ap, 0);
    k_softmax<<<BB, 256>>>(b_ac, 1);
    k_context<<<BB, 256>>>(prev, 0);
    k_context<<<BB, 256>>>(encc, 1);
    k_gates_part<<<dim3(32,5), 256, SMEM_BYTES>>>();
    k_gates_reduce<<<(BB*G4H)/256, 256>>>(b_ih, b_hh);
    k_lstm<<<(BB*HH)/256, 256>>>(c0, out, write_state);
    k_out_part<<<dim3(79,2), 256, SMEM_BYTES>>>();
    k_out_reduce<<<(BB*VV + 255)/256, 256>>>(b_out, out);
}

// round 17
// speedup vs baseline: 1.7101x; 1.1376x over previous
#include <cuda_runtime.h>
#include <cuda_bf16.h>
#include <cstdint>
#include <math.h>

// Problem constants
#define BB 128
#define SS 256
#define HH 1024
#define EE 512
#define ENVD 896
#define VV 10000
#define INSZ 3456          // E + H + H + ENV
#define MATT (SS*BB)       // 32768
#define G4H 4096

// fp32 -> tf32 (rna) kept in a float container.
__device__ __forceinline__ float tf32f(float x) {
    unsigned r;
    asm("cvt.rna.tf32.f32 %0, %1;" : "=r"(r) : "f"(x));
    return __uint_as_float(r);
}
__device__ __forceinline__ unsigned short bfbits(float x) {
    __nv_bfloat16 h = __float2bfloat16_rn(x);
    return *reinterpret_cast<unsigned short*>(&h);
}
__device__ __forceinline__ uint32_t smem_u32(const void* p) {
    uint32_t a;
    asm("{ .reg .u64 t; cvta.to.shared.u64 t, %1; cvt.u32.u64 %0, t; }" : "=r"(a) : "l"(p));
    return a;
}

// ---------------- scratch (device globals; DEVICE-CODE-ONLY references) ----------------
__device__ float g_x[BB*INSZ];
__device__ float g_hp[BB*HH];
__device__ float g_hc[BB*HH];
__device__ float g_spP[8*MATT];
__device__ float g_spC[8*MATT];
__device__ float g_wP[MATT];
__device__ float g_wC[MATT];
__device__ float g_gpart[5*BB*G4H];
__device__ float g_gates[BB*G4H];
__device__ float g_opart[2*BB*VV];
__device__ float g_h1[BB*HH];
__device__ float g_c1[BB*HH];
// tf32-pre-rounded operands (gates / out / hproj)
__device__ float g_Whp[HH*HH];
__device__ float g_Whc[HH*HH];
__device__ float g_Wih[INSZ*G4H];
__device__ float g_Whh[HH*G4H];
__device__ float g_Wo[HH*VV];
__device__ float g_h0r[BB*HH];
// bf16 operands for attention GEMM
__device__ __nv_bfloat16 g_encPb[(size_t)MATT*HH];
__device__ __nv_bfloat16 g_encCb[(size_t)MATT*HH];
__device__ __nv_bfloat16 g_WepT[HH*HH];   // transposed [n][k]
__device__ __nv_bfloat16 g_WecT[HH*HH];

// ---------------- fused tf32 pre-round: all six operands in one launch ----------------
// float4 segment ends (CORRECTED): Whp 262144, Whc 524288, Wih 4063232,
// Whh 5111808, Wo 7671808, h0r 7704576.
#define RND_TOTAL 7704576
__global__ void __launch_bounds__(256) k_round_all(
    const float* __restrict__ s0, const float* __restrict__ s1,
    const float* __restrict__ s2, const float* __restrict__ s3,
    const float* __restrict__ s4, const float* __restrict__ s5)
{
    int i = blockIdx.x*256 + threadIdx.x;
    const float4* src; float4* dst; int off;
    if (i < 262144)       { src = (const float4*)s0; dst = (float4*)g_Whp; off = 0; }
    else if (i < 524288)  { src = (const float4*)s1; dst = (float4*)g_Whc; off = 262144; }
    else if (i < 4063232) { src = (const float4*)s2; dst = (float4*)g_Wih; off = 524288; }
    else if (i < 5111808) { src = (const float4*)s3; dst = (float4*)g_Whh; off = 4063232; }
    else if (i < 7671808) { src = (const float4*)s4; dst = (float4*)g_Wo;  off = 5111808; }
    else if (i < 7704576) { src = (const float4*)s5; dst = (float4*)g_h0r; off = 7671808; }
    else return;
    int j = i - off;
    float4 v = src[j];
    float4 w;
    w.x = tf32f(v.x); w.y = tf32f(v.y); w.z = tf32f(v.z); w.w = tf32f(v.w);
    dst[j] = w;
}

__global__ void __launch_bounds__(256) k_enc_bf16(
    const float* __restrict__ srcP, const float* __restrict__ srcC)
{
    size_t i = (size_t)blockIdx.x*256 + threadIdx.x;
    const float* src = blockIdx.y ? srcC : srcP;
    __nv_bfloat16* dst = blockIdx.y ? g_encCb : g_encPb;
    float4 v = ((const float4*)src)[i];
    uint2 o;
    o.x = (uint32_t)bfbits(v.x) | ((uint32_t)bfbits(v.y) << 16);
    o.y = (uint32_t)bfbits(v.z) | ((uint32_t)bfbits(v.w) << 16);
    ((uint2*)dst)[i] = o;
}

// transpose W [k][n] fp32 -> Wt [n][k] bf16 (32x32 tiles via smem)
__global__ void __launch_bounds__(256) k_wT(
    const float* __restrict__ Wp, const float* __restrict__ Wc)
{
    __shared__ float tile[32][33];
    const float* W = blockIdx.z ? Wc : Wp;
    int n0 = blockIdx.x*32, k0 = blockIdx.y*32;
    int tx = threadIdx.x & 31, ty = threadIdx.x >> 5;
    #pragma unroll
    for (int i = 0; i < 32; i += 8)
        tile[ty+i][tx] = W[(size_t)(k0+ty+i)*HH + n0+tx];
    __syncthreads();
    __nv_bfloat16* Wt = blockIdx.z ? g_WecT : g_WepT;
    #pragma unroll
    for (int i = 0; i < 32; i += 8)
        Wt[(size_t)(n0+ty+i)*HH + k0+tx] = __float2bfloat16_rn(tile[tx][ty+i]);
}

// ---------------- cp.async primitives ----------------
__device__ __forceinline__ void cpa16(uint32_t dst, const void* src) {
    asm volatile("cp.async.cg.shared.global [%0], [%1], 16;" :: "r"(dst), "l"(src));
}
__device__ __forceinline__ void cpa16z(uint32_t dst, const void* src, int bytes) {
    asm volatile("cp.async.cg.shared.global [%0], [%1], 16, %2;" :: "r"(dst), "l"(src), "r"(bytes));
}
#define CPA_COMMIT() asm volatile("cp.async.commit_group;" ::: "memory")
#define CPA_WAIT1()  asm volatile("cp.async.wait_group 1;" ::: "memory")
#define CPA_WAIT0()  asm volatile("cp.async.wait_group 0;" ::: "memory")

// ---------------- tf32 mma.sync GEMM core, 3-stage cp.async (hproj/gates/out) ----------------
#define AS_LD 36
#define BS_LD 136
#define STAGE_F (128*AS_LD + 32*BS_LD)
#define SMEM_BYTES (3*STAGE_F*4)

__device__ __forceinline__ void mma_tf32(float* c, const unsigned* a, unsigned b0, unsigned b1) {
    asm volatile(
        "mma.sync.aligned.m16n8k8.row.col.f32.tf32.tf32.f32 "
        "{%0,%1,%2,%3},{%4,%5,%6,%7},{%8,%9},{%0,%1,%2,%3};"
        : "+f"(c[0]), "+f"(c[1]), "+f"(c[2]), "+f"(c[3])
        : "r"(a[0]), "r"(a[1]), "r"(a[2]), "r"(a[3]), "r"(b0), "r"(b1));
}

__device__ __forceinline__ void issue_tile_async(
    uint32_t stage_u,
    const float* __restrict__ A, int lda,
    const float* __restrict__ Wn, int ldw,
    int kt, int nvalid, int t)
{
    uint32_t As_u = stage_u;
    uint32_t Bs_u = stage_u + 128*AS_LD*4;
    #pragma unroll
    for (int j = 0; j < 4; j++) {
        int idx = t + 256*j;
        int row = idx >> 3, cq = (idx & 7) << 2;
        cpa16(As_u + (uint32_t)(row*AS_LD + cq)*4, A + (size_t)row*lda + kt + cq);
    }
    #pragma unroll
    for (int j = 0; j < 4; j++) {
        int idx = t + 256*j;
        int kr = idx >> 5, nq = (idx & 31) << 2;
        const float* src = Wn + (size_t)(kt + kr)*ldw + nq;
        uint32_t dst = Bs_u + (uint32_t)(kr*BS_LD + nq)*4;
        if (nvalid >= 128) {
            cpa16(dst, src);
        } else {
            int rem = nvalid - nq;
            int bytes = rem >= 4 ? 16 : (rem > 0 ? rem*4 : 0);
            cpa16z(dst, rem > 0 ? src : Wn, bytes);
        }
    }
}

__device__ __forceinline__ void compute_tile(
    const float* __restrict__ As, const float* __restrict__ Bs,
    float (&acc)[2][8][4], int mwarp, int nwarp, int lq, int lp)
{
    #pragma unroll
    for (int k8 = 0; k8 < 32; k8 += 8) {
        unsigned a[2][4];
        #pragma unroll
        for (int mt = 0; mt < 2; mt++) {
            int r = mwarp*32 + mt*16 + lq;
            int c = k8 + lp;
            a[mt][0] = __float_as_uint(As[r*AS_LD + c]);
            a[mt][1] = __float_as_uint(As[(r+8)*AS_LD + c]);
            a[mt][2] = __float_as_uint(As[r*AS_LD + c + 4]);
            a[mt][3] = __float_as_uint(As[(r+8)*AS_LD + c + 4]);
        }
        #pragma unroll
        for (int nt = 0; nt < 8; nt++) {
            int n  = nwarp*64 + nt*8 + lq;
            int kb = k8 + lp;
            unsigned b0 = __float_as_uint(Bs[kb*BS_LD + n]);
            unsigned b1 = __float_as_uint(Bs[(kb+4)*BS_LD + n]);
            mma_tf32(acc[0][nt], a[0], b0, b1);
            mma_tf32(acc[1][nt], a[1], b0, b1);
        }
    }
}

__device__ __forceinline__ void mma_core_async(
    const float* __restrict__ A, int lda,
    const float* __restrict__ Wn, int ldw,
    int k0, int k1, int nvalid,
    float (&acc)[2][8][4], float* smp)
{
    const int t = threadIdx.x;
    const int lane = t & 31, wid = t >> 5;
    const int mwarp = wid & 3, nwarp = wid >> 2;
    const int lq = lane >> 2, lp = lane & 3;
    const uint32_t smp_u = smem_u32(smp);
    const int nsteps = (k1 - k0) >> 5;

    issue_tile_async(smp_u, A, lda, Wn, ldw, k0, nvalid, t);
    CPA_COMMIT();
    if (nsteps > 1)
        issue_tile_async(smp_u + STAGE_F*4, A, lda, Wn, ldw, k0 + 32, nvalid, t);
    CPA_COMMIT();

    for (int i = 0; i < nsteps; i++) {
        CPA_WAIT1();
        __syncthreads();
        if (i + 2 < nsteps) {
            int s = (i + 2) % 3;
            issue_tile_async(smp_u + (uint32_t)s*STAGE_F*4, A, lda, Wn, ldw,
                             k0 + 32*(i+2), nvalid, t);
        }
        CPA_COMMIT();
        int cs = i % 3;
        compute_tile(smp + cs*STAGE_F, smp + cs*STAGE_F + 128*AS_LD,
                     acc, mwarp, nwarp, lq, lp);
    }
}

// ---------------- bf16 mma.sync GEMM core: K-step 64, ldmatrix, 2-stage ----------------
#define ABS_LD 72                            // bf16 elems/row (144B)
#define BSTAGE (2*128*ABS_LD*2)              // A+B stage bytes = 36864
#define ATTN_SMEM (2*BSTAGE)                 // 73728

__device__ __forceinline__ void mma_bf16(float* c, const unsigned* a, unsigned b0, unsigned b1) {
    asm volatile(
        "mma.sync.aligned.m16n8k16.row.col.f32.bf16.bf16.f32 "
        "{%0,%1,%2,%3},{%4,%5,%6,%7},{%8,%9},{%0,%1,%2,%3};"
        : "+f"(c[0]), "+f"(c[1]), "+f"(c[2]), "+f"(c[3])
        : "r"(a[0]), "r"(a[1]), "r"(a[2]), "r"(a[3]), "r"(b0), "r"(b1));
}
__device__ __forceinline__ void ldsm4(uint32_t a, unsigned &r0, unsigned &r1, unsigned &r2, unsigned &r3) {
    asm volatile("ldmatrix.sync.aligned.m8n8.x4.shared.b16 {%0,%1,%2,%3}, [%4];"
        : "=r"(r0), "=r"(r1), "=r"(r2), "=r"(r3) : "r"(a));
}

__device__ __forceinline__ void issue_tile_bf16(
    uint32_t stage_u,
    const __nv_bfloat16* __restrict__ A,
    const __nv_bfloat16* __restrict__ Bt,
    int kt, int t)
{
    uint32_t As_u = stage_u;
    uint32_t Bs_u = stage_u + 128*ABS_LD*2;
    #pragma unroll
    for (int j = 0; j < 4; j++) {
        int idx = t + 256*j;
        int row = idx >> 3, c8 = (idx & 7) << 3;
        cpa16(As_u + (uint32_t)(row*144 + c8*2), A + (size_t)row*HH + kt + c8);
    }
    #pragma unroll
    for (int j = 0; j < 4; j++) {
        int idx = t + 256*j;
        int n = idx >> 3, c8 = (idx & 7) << 3;
        cpa16(Bs_u + (uint32_t)(n*144 + c8*2), Bt + (size_t)n*HH + kt + c8);
    }
}

// ldmatrix fragment mapping identical to round 15 (validated), ABS_LD rescaled.
__device__ __forceinline__ void compute_tile_bf16(
    uint32_t As_u, uint32_t Bs_u,
    float (&acc)[2][8][4], uint32_t a_off, uint32_t b_off)
{
    #pragma unroll
    for (int s = 0; s < 4; s++) {          // 4 x k16 = K64
        unsigned a0[4], a1[4];
        ldsm4(As_u + a_off + (uint32_t)(s*16)*2,             a0[0], a0[1], a0[2], a0[3]);
        ldsm4(As_u + a_off + (uint32_t)(16*ABS_LD + s*16)*2, a1[0], a1[1], a1[2], a1[3]);
        unsigned b[8][2];
        #pragma unroll
        for (int p = 0; p < 4; p++) {
            ldsm4(Bs_u + b_off + (uint32_t)(p*16*ABS_LD + s*16)*2,
                  b[2*p][0], b[2*p][1], b[2*p+1][0], b[2*p+1][1]);
        }
        #pragma unroll
        for (int nt = 0; nt < 8; nt++) {
            mma_bf16(acc[0][nt], a0, b[nt][0], b[nt][1]);
            mma_bf16(acc[1][nt], a1, b[nt][0], b[nt][1]);
        }
    }
}

__device__ __forceinline__ void mma_core_bf16(
    const __nv_bfloat16* __restrict__ A,
    const __nv_bfloat16* __restrict__ Bt,
    float (&acc)[2][8][4], char* smp)
{
    const int t = threadIdx.x;
    const int lane = t & 31, wid = t >> 5;
    const int mwarp = wid & 3, nwarp = wid >> 2;
    const uint32_t smp_u = smem_u32(smp);
    const int nsteps = HH / 64;   // 16

    const int arow = mwarp*32 + ((lane>>3)&1)*8 + (lane&7);
    const int acol = (lane>>4)*8;
    const uint32_t a_off = (uint32_t)(arow*ABS_LD + acol)*2;
    const int brow = nwarp*64 + ((lane>>4)&1)*8 + (lane&7);
    const int bcol = ((lane>>3)&1)*8;
    const uint32_t b_off = (uint32_t)(brow*ABS_LD + bcol)*2;

    issue_tile_bf16(smp_u, A, Bt, 0, t);
    CPA_COMMIT();

    for (int i = 0; i < nsteps; i++) {
        CPA_WAIT0();              // stage i landed
        __syncthreads();          // visible to all; buf (i+1)&1's readers (iter i-1) done
        if (i + 1 < nsteps) {
            issue_tile_bf16(smp_u + (uint32_t)((i+1)&1)*BSTAGE, A, Bt, 64*(i+1), t);
            CPA_COMMIT();         // overlaps with compute below
        }
        uint32_t As_u = smp_u + (uint32_t)(i&1)*BSTAGE;
        compute_tile_bf16(As_u, As_u + 128*ABS_LD*2, acc, a_off, b_off);
    }
}

// ---------------- embedding gather + environment copy (tf32-rounded into x) ----------------
__global__ void __launch_bounds__(256) k_embed(
    const int* __restrict__ ids, const float* __restrict__ emb,
    const float* __restrict__ env)
{
    int b = blockIdx.x, t = threadIdx.x;
    int id = ids[b];
    float* xr = g_x + (size_t)b*INSZ;
    for (int c = t; c < EE; c += 256)   xr[c]        = tf32f(emb[(size_t)id*EE + c]);
    for (int c = t; c < ENVD; c += 256) xr[2560 + c] = tf32f(env[(size_t)b*ENVD + c]);
}

// ---------------- h projections: g_hp/g_hc = h@W + b1 + b2 ----------------
__global__ void __launch_bounds__(256) k_hproj(
    const float* __restrict__ b1p, const float* __restrict__ b2p,
    const float* __restrict__ b1c, const float* __restrict__ b2c)
{
    extern __shared__ float smem[];
    float acc[2][8][4] = {};
    int n0 = blockIdx.x * 128;
    const float* W  = blockIdx.y ? g_Whc : g_Whp;
    const float* b1 = blockIdx.y ? b1c : b1p;
    const float* b2 = blockIdx.y ? b2c : b2p;
    float* out      = blockIdx.y ? g_hc : g_hp;

    mma_core_async(g_h0r, HH, W + n0, HH, 0, HH, 128, acc, smem);

    int t = threadIdx.x, lane = t & 31, wid = t >> 5;
    int mwarp = wid & 3, nwarp = wid >> 2, lq = lane >> 2, lp = lane & 3;
    #pragma unroll
    for (int mt = 0; mt < 2; mt++)
        #pragma unroll
        for (int nt = 0; nt < 8; nt++) {
            int r  = mwarp*32 + mt*16 + lq;
            int cb = n0 + nwarp*64 + nt*8 + lp*2;
            out[(size_t)r*HH + cb]       = acc[mt][nt][0] + b1[cb]   + b2[cb];
            out[(size_t)r*HH + cb+1]     = acc[mt][nt][1] + b1[cb+1] + b2[cb+1];
            out[(size_t)(r+8)*HH + cb]   = acc[mt][nt][2] + b1[cb]   + b2[cb];
            out[(size_t)(r+8)*HH + cb+1] = acc[mt][nt][3] + b1[cb+1] + b2[cb+1];
        }
}

// ---------------- fused attention: bf16 GEMM (ldmatrix, K64) + tanh·wa epilogue ----------------
// grid (8, 256, 2): z selects prev/cur attention.
__global__ void __launch_bounds__(256) k_attn_score(
    const float* __restrict__ waP, const float* __restrict__ waC)
{
    extern __shared__ char smemc[];
    __shared__ float red[128][8];
    float acc[2][8][4] = {};
    int n0 = blockIdx.x * 128;
    int m0 = blockIdx.y * 128;
    int sel = blockIdx.z;

    const __nv_bfloat16* enc = sel ? g_encCb : g_encPb;
    const __nv_bfloat16* Wt  = sel ? g_WecT  : g_WepT;
    const float* wa          = sel ? waC : waP;

    mma_core_bf16(enc + (size_t)m0*HH, Wt + (size_t)n0*HH, acc, smemc);

    const float* hp    = sel ? g_hc : g_hp;
    float*       spart = sel ? g_spC : g_spP;

    int t = threadIdx.x, lane = t & 31, wid = t >> 5;
    int mwarp = wid & 3, nwarp = wid >> 2, lq = lane >> 2, lp = lane & 3;

    float part[2][2] = {};
    #pragma unroll
    for (int mt = 0; mt < 2; mt++) {
        int r0 = mwarp*32 + mt*16 + lq;
        const float* hp0 = hp + (size_t)r0*HH;
        const float* hp8 = hp + (size_t)(r0+8)*HH;
        #pragma unroll
        for (int nt = 0; nt < 8; nt++) {
            int cb = n0 + nwarp*64 + nt*8 + lp*2;
            float w0 = wa[cb], w1 = wa[cb+1];
            part[mt][0] += tanhf(acc[mt][nt][0] + hp0[cb])   * w0
                         + tanhf(acc[mt][nt][1] + hp0[cb+1]) * w1;
            part[mt][1] += tanhf(acc[mt][nt][2] + hp8[cb])   * w0
                         + tanhf(acc[mt][nt][3] + hp8[cb+1]) * w1;
        }
    }
    int slot = nwarp*4 + lp;
    #pragma unroll
    for (int mt = 0; mt < 2; mt++) {
        red[mwarp*32 + mt*16 + lq][slot]     = part[mt][0];
        red[mwarp*32 + mt*16 + lq + 8][slot] = part[mt][1];
    }
    __syncthreads();
    if (t < 128) {
        float s = 0.f;
        #pragma unroll
        for (int p = 0; p < 8; p++) s += red[t][p];
        spart[(size_t)blockIdx.x*MATT + m0 + t] = s;
    }
}

// ---------------- softmax over S per batch row (grid.y selects attention) ----------------
__global__ void __launch_bounds__(256) k_softmax(
    const float* __restrict__ b_aP, const float* __restrict__ b_aC)
{
    int sel = blockIdx.y;
    const float* spart = sel ? g_spC : g_spP;
    float*       wout  = sel ? g_wC : g_wP;
    const float* b_a   = sel ? b_aC : b_aP;
    int b = blockIdx.x, s = threadIdx.x;
    float sc = *b_a;
    #pragma unroll
    for (int p = 0; p < 8; p++) sc += spart[(size_t)p*MATT + s*BB + b];

    __shared__ float sm[256];
    sm[s] = sc; __syncthreads();
    for (int o = 128; o > 0; o >>= 1) {
        if (s < o) sm[s] = fmaxf(sm[s], sm[s+o]);
        __syncthreads();
    }
    float mx = sm[0]; __syncthreads();
    float e = expf(sc - mx);
    sm[s] = e; __syncthreads();
    for (int o = 128; o > 0; o >>= 1) {
        if (s < o) sm[s] += sm[s+o];
        __syncthreads();
    }
    wout[s*BB + b] = e / sm[0];
}

// ---------------- context (grid.y selects attention) ----------------
__global__ void __launch_bounds__(256) k_context(
    const float* __restrict__ encP, const float* __restrict__ encC)
{
    int sel = blockIdx.y;
    const float* enc = sel ? encC : encP;
    const float* w   = sel ? g_wC : g_wP;
    const int   off  = sel ? 1536 : 512;
    int b = blockIdx.x, t = threadIdx.x;
    __shared__ float ws[256];
    ws[t] = w[t*BB + b];
    __syncthreads();
    const float4* e4 = (const float4*)enc;
    float4 acc = make_float4(0.f, 0.f, 0.f, 0.f);
    #pragma unroll 8
    for (int s = 0; s < SS; s++) {
        float wv = ws[s];
        float4 v = e4[((size_t)(s*BB + b))*(HH/4) + t];
        acc.x = fmaf(wv, v.x, acc.x);
        acc.y = fmaf(wv, v.y, acc.y);
        acc.z = fmaf(wv, v.z, acc.z);
        acc.w = fmaf(wv, v.w, acc.w);
    }
    float4 rr;
    rr.x = tf32f(acc.x); rr.y = tf32f(acc.y); rr.z = tf32f(acc.z); rr.w = tf32f(acc.w);
    *(float4*)(g_x + (size_t)b*INSZ + off + t*4) = rr;
}

// ---------------- gates GEMM, K split into 5 chunks ----------------
__global__ void __launch_bounds__(256) k_gates_part()
{
    extern __shared__ float smem[];
    float acc[2][8][4] = {};
    int n0 = blockIdx.x * 128;
    int ch = blockIdx.y;
    if (ch < 4)
        mma_core_async(g_x, INSZ, g_Wih + n0, G4H, ch*864, (ch+1)*864, 128, acc, smem);
    else
        mma_core_async(g_h0r, HH, g_Whh + n0, G4H, 0, HH, 128, acc, smem);

    int t = threadIdx.x, lane = t & 31, wid = t >> 5;
    int mwarp = wid & 3, nwarp = wid >> 2, lq = lane >> 2, lp = lane & 3;
    float* dst = g_gpart + (size_t)ch*BB*G4H;
    #pragma unroll
    for (int mt = 0; mt < 2; mt++)
        #pragma unroll
        for (int nt = 0; nt < 8; nt++) {
            int r  = mwarp*32 + mt*16 + lq;
            int cb = n0 + nwarp*64 + nt*8 + lp*2;
            *(float2*)(dst + (size_t)r*G4H + cb)     = make_float2(acc[mt][nt][0], acc[mt][nt][1]);
            *(float2*)(dst + (size_t)(r+8)*G4H + cb) = make_float2(acc[mt][nt][2], acc[mt][nt][3]);
        }
}

__global__ void __launch_bounds__(256) k_gates_reduce(
    const float* __restrict__ b_ih, const float* __restrict__ b_hh)
{
    int idx = blockIdx.x*256 + threadIdx.x;
    int n = idx & (G4H-1);
    float s = b_ih[n] + b_hh[n];
    #pragma unroll
    for (int p = 0; p < 5; p++) s += g_gpart[(size_t)p*BB*G4H + idx];
    g_gates[idx] = s;
}

// ---------------- LSTM cell elementwise (double transcendentals: exact) ----------------
__global__ void __launch_bounds__(256) k_lstm(
    const float* __restrict__ c0, float* __restrict__ d_out, int write_out)
{
    int idx = blockIdx.x*256 + threadIdx.x;
    int b = idx >> 10, n = idx & 1023;
    const float* g = g_gates + (size_t)b*G4H;
    double gi = g[n], gf = g[1024+n], gg = g[2048+n], go = g[3072+n];
    double si = 1.0/(1.0 + exp(-gi));
    double sf = 1.0/(1.0 + exp(-gf));
    double so = 1.0/(1.0 + exp(-go));
    double c1 = sf * (double)c0[idx] + si * tanh(gg);
    double h1 = so * tanh(c1);
    float h1f = (float)h1;
    g_h1[idx] = tf32f(h1f);
    g_c1[idx] = (float)c1;
    if (write_out) {
        d_out[1280000 + idx] = h1f;
        d_out[1411072 + idx] = (float)c1;
    }
}

// ---------------- output GEMM, K split 2, N bounds ----------------
__global__ void __launch_bounds__(256) k_out_part()
{
    extern __shared__ float smem[];
    float acc[2][8][4] = {};
    int n0 = blockIdx.x * 128;
    int nvalid = VV - n0; if (nvalid > 128) nvalid = 128;
    int ks = blockIdx.y;
    mma_core_async(g_h1, HH, g_Wo + n0, VV, ks*512, (ks+1)*512, nvalid, acc, smem);

    int t = threadIdx.x, lane = t & 31, wid = t >> 5;
    int mwarp = wid & 3, nwarp = wid >> 2, lq = lane >> 2, lp = lane & 3;
    float* dst = g_opart + (size_t)ks*BB*VV;
    #pragma unroll
    for (int mt = 0; mt < 2; mt++)
        #pragma unroll
        for (int nt = 0; nt < 8; nt++) {
            int r  = mwarp*32 + mt*16 + lq;
            int cb = n0 + nwarp*64 + nt*8 + lp*2;
            if (cb + 1 < VV) {
                *(float2*)(dst + (size_t)r*VV + cb)     = make_float2(acc[mt][nt][0], acc[mt][nt][1]);
                *(float2*)(dst + (size_t)(r+8)*VV + cb) = make_float2(acc[mt][nt][2], acc[mt][nt][3]);
            }
        }
}

__global__ void __launch_bounds__(256) k_out_reduce(
    const float* __restrict__ b_out, float* __restrict__ out)
{
    int idx = blockIdx.x*256 + threadIdx.x;
    if (idx < BB*VV) {
        int n = idx % VV;
        out[idx] = g_opart[idx] + g_opart[(size_t)BB*VV + idx] + b_out[n];
    }
}

// ---------------- launch ----------------
extern "C" void kernel_launch(void* const* d_in, const int* in_sizes, int n_in,
                              void* d_out, int out_size)
{
    const int*   ids  = (const int*)d_in[0];
    const float* prev = (const float*)d_in[1];
    const float* encc = (const float*)d_in[2];
    const float* env  = (const float*)d_in[3];
    const float* h0   = (const float*)d_in[4];
    const float* c0   = (const float*)d_in[5];
    const float* emb  = (const float*)d_in[6];
    const float* W_hp = (const float*)d_in[7];
    const float* b_hp = (const float*)d_in[8];
    const float* W_ep = (const float*)d_in[9];
    const float* b_ep = (const float*)d_in[10];
    const float* w_ap = (const float*)d_in[11];
    const float* b_ap = (const float*)d_in[12];
    const float* W_hc = (const float*)d_in[13];
    const float* b_hc = (const float*)d_in[14];
    const float* W_ec = (const float*)d_in[15];
    const float* b_ec = (const float*)d_in[16];
    const float* w_ac = (const float*)d_in[17];
    const float* b_ac = (const float*)d_in[18];

    const float* W_ih = (const float*)d_in[19];
    const float* W_hh; const float* b_ih; const float* b_hh;
    if (in_sizes[20] == 1024*4096) {
        W_hh = (const float*)d_in[20];
        b_ih = (const float*)d_in[21];
        b_hh = (const float*)d_in[22];
    } else {
        b_ih = (const float*)d_in[20];
        W_hh = (const float*)d_in[21];
        b_hh = (const float*)d_in[22];
    }
    const float* W_out = (const float*)d_in[23];
    const float* b_out = (const float*)d_in[24];

    float* out = (float*)d_out;
    int write_state = (out_size >= 1542144) ? 1 : 0;

    cudaFuncSetAttribute(k_hproj,      cudaFuncAttributeMaxDynamicSharedMemorySize, SMEM_BYTES);
    cudaFuncSetAttribute(k_attn_score, cudaFuncAttributeMaxDynamicSharedMemorySize, ATTN_SMEM);
    cudaFuncSetAttribute(k_gates_part, cudaFuncAttributeMaxDynamicSharedMemorySize, SMEM_BYTES);
    cudaFuncSetAttribute(k_out_part,   cudaFuncAttributeMaxDynamicSharedMemorySize, SMEM_BYTES);

    // 0. operand prep: bf16 for attention, tf32 for the rest (one fused launch)
    k_enc_bf16<<<dim3(32768,2), 256>>>(prev, encc);
    k_wT<<<dim3(32,32,2), 256>>>(W_ep, W_ec);
    k_round_all<<<(RND_TOTAL+255)/256, 256>>>(W_hp, W_hc, W_ih, W_hh, W_out, h0);

    k_embed<<<BB, 256>>>(ids, emb, env);
    k_hproj<<<dim3(8,2), 256, SMEM_BYTES>>>(b_hp, b_ep, b_hc, b_ec);
    k_attn_score<<<dim3(8,256,2), 256, ATTN_SMEM>>>(w_ap, w_ac);
    k_softmax<<<dim3(BB,2), 256>>>(b_ap, b_ac);
    k_context<<<dim3(BB,2), 256>>>(prev, encc);
    k_gates_part<<<dim3(32,5), 256, SMEM_BYTES>>>();
    k_gates_reduce<<<(BB*G4H)/256, 256>>>(b_ih, b_hh);
    k_lstm<<<(BB*HH)/256, 256>>>(c0, out, write_state);
    k_out_part<<<dim3(79,2), 256, SMEM_BYTES>>>();
    k_out_reduce<<<(BB*VV + 255)/256, 256>>>(b_out, out);
}